// round 5
// baseline (speedup 1.0000x reference)
#include <cuda_runtime.h>
#include <math.h>

#define TT 512
#define NN 128
#define II 256
#define HH 512
#define CC 128
#define NH (NN*HH)
#define RNN_BLOCKS 128
#define H_OFF (NN*CC)

__device__ float g_xp[TT*NN*HH];      // xproj base, RED-accumulated per step
__device__ float g_out0[TT*NN*HH];    // layer-0 outputs
__device__ float g_h[NH];             // final hidden per layer (+ h0 seed)
__device__ int   g_cnt[TT];
__device__ int   g_arrive[RNN_BLOCKS];

__global__ void count_kernel(const int* __restrict__ len) {
    int t = threadIdx.x, c = 0;
    #pragma unroll 8
    for (int n = 0; n < NN; n++) c += (len[n] > t) ? 1 : 0;
    g_cnt[t] = c;
}

// init h from h0 AND reset barrier flags (required per launch / per graph replay)
__global__ void init_h_kernel(const float* __restrict__ h0, int layer) {
    int i = blockIdx.x * blockDim.x + threadIdx.x;
    if (i < NH) g_h[i] = h0[layer * NH + i];
    if (blockIdx.x == 0 && threadIdx.x < RNN_BLOCKS) g_arrive[threadIdx.x] = 0;
}

__global__ void copy_h_kernel(float* __restrict__ dout, int layer) {
    int i = blockIdx.x * blockDim.x + threadIdx.x;
    if (i < NH) dout[H_OFF + layer * NH + i] = g_h[i];
}

// ---- GEMM + bias: C[m,j] = A[m,:K].W[j,:K] + b1 (+b2). 64x128 tile, 128 thr,
// 8x8 microtile, double-buffered smem. asel: 0=Aptr 1=g_out0 2=g_h; csel: 0=g_xp 1=Cptr.
__global__ __launch_bounds__(128)
void gemm64(const float* __restrict__ Aptr, int asel,
            const float* __restrict__ W,
            const float* __restrict__ b1, const float* __restrict__ b2,
            float* __restrict__ Cptr, int csel, int K, int Hout, int useCnt)
{
    const float* A = (asel == 0) ? Aptr : ((asel == 1) ? g_out0 : g_h);
    float* C = (csel == 0) ? g_xp : Cptr;

    int row0;
    if (useCnt) {
        int t = blockIdx.y >> 1, nt = blockIdx.y & 1;
        if (nt * 64 >= g_cnt[t]) return;
        row0 = t * NN + nt * 64;
    } else {
        row0 = blockIdx.y * 64;
    }
    int j0 = blockIdx.x * 128;
    int tid = threadIdx.x;

    __shared__ float As[2][8][68];
    __shared__ float Bs[2][8][132];

    int ar = tid >> 1;
    int ak = (tid & 1) * 4;
    const float* Ap = A + (size_t)(row0 + ar) * K + ak;
    const float* Wp = W + (size_t)(j0 + tid) * K;
    int KT = K >> 3;

    float4 a_r  = *(const float4*)(Ap);
    float4 b_r0 = *(const float4*)(Wp);
    float4 b_r1 = *(const float4*)(Wp + 4);
    As[0][ak+0][ar] = a_r.x; As[0][ak+1][ar] = a_r.y;
    As[0][ak+2][ar] = a_r.z; As[0][ak+3][ar] = a_r.w;
    Bs[0][0][tid] = b_r0.x; Bs[0][1][tid] = b_r0.y;
    Bs[0][2][tid] = b_r0.z; Bs[0][3][tid] = b_r0.w;
    Bs[0][4][tid] = b_r1.x; Bs[0][5][tid] = b_r1.y;
    Bs[0][6][tid] = b_r1.z; Bs[0][7][tid] = b_r1.w;
    __syncthreads();

    int tm = tid & 7;
    int tj = tid >> 3;
    float acc[8][8] = {};

    for (int kt = 0; kt < KT; kt++) {
        int cur = kt & 1;
        bool nxt = (kt + 1 < KT);
        if (nxt) {
            int k0 = (kt + 1) << 3;
            a_r  = *(const float4*)(Ap + k0);
            b_r0 = *(const float4*)(Wp + k0);
            b_r1 = *(const float4*)(Wp + k0 + 4);
        }
        #pragma unroll
        for (int kk = 0; kk < 8; kk++) {
            float4 a0 = *(const float4*)&As[cur][kk][tm*8];
            float4 a1 = *(const float4*)&As[cur][kk][tm*8+4];
            float4 b0 = *(const float4*)&Bs[cur][kk][tj*8];
            float4 b1v= *(const float4*)&Bs[cur][kk][tj*8+4];
            float av[8] = {a0.x,a0.y,a0.z,a0.w,a1.x,a1.y,a1.z,a1.w};
            float bv[8] = {b0.x,b0.y,b0.z,b0.w,b1v.x,b1v.y,b1v.z,b1v.w};
            #pragma unroll
            for (int i = 0; i < 8; i++)
                #pragma unroll
                for (int j = 0; j < 8; j++)
                    acc[i][j] = fmaf(av[i], bv[j], acc[i][j]);
        }
        if (nxt) {
            int nb = cur ^ 1;
            As[nb][ak+0][ar] = a_r.x; As[nb][ak+1][ar] = a_r.y;
            As[nb][ak+2][ar] = a_r.z; As[nb][ak+3][ar] = a_r.w;
            Bs[nb][0][tid] = b_r0.x; Bs[nb][1][tid] = b_r0.y;
            Bs[nb][2][tid] = b_r0.z; Bs[nb][3][tid] = b_r0.w;
            Bs[nb][4][tid] = b_r1.x; Bs[nb][5][tid] = b_r1.y;
            Bs[nb][6][tid] = b_r1.z; Bs[nb][7][tid] = b_r1.w;
        }
        __syncthreads();
    }

    int jc = j0 + tj * 8;
    float bb[8];
    #pragma unroll
    for (int j = 0; j < 8; j++)
        bb[j] = b1[jc+j] + (b2 ? b2[jc+j] : 0.0f);
    #pragma unroll
    for (int i = 0; i < 8; i++) {
        int row = row0 + tm * 8 + i;
        float4 v0 = make_float4(acc[i][0]+bb[0], acc[i][1]+bb[1],
                                acc[i][2]+bb[2], acc[i][3]+bb[3]);
        float4 v1 = make_float4(acc[i][4]+bb[4], acc[i][5]+bb[5],
                                acc[i][6]+bb[6], acc[i][7]+bb[7]);
        *(float4*)(C + (size_t)row * Hout + jc)     = v0;
        *(float4*)(C + (size_t)row * Hout + jc + 4) = v1;
    }
}

// ---- persistent recurrence v2: ONE grid barrier per step ----------------------
// 128 CTAs = 16 j-tiles(32 cols) x 8 k-chunks(64). Per step t:
//   stage: read xp[t-1] (accumulated), tanh -> h[t-1]; writers persist to
//          g_h / g_out0; store active rows to smem
//   gemm:  partial h[t-1] @ Whh^T for this (j,k) tile, RED.ADD into xp[t]
//   barrier (flag array, no atomic contention)
__global__ __launch_bounds__(256)
void rnn2(const float* __restrict__ Whh, int storeOut)
{
    __shared__ float Ws[64][32];
    __shared__ float hs[64][128];
    __shared__ int   cs[TT];

    int tid = threadIdx.x, cta = blockIdx.x;
    int jt = cta & 15, kc = cta >> 4;
    int j0 = jt * 32, k0 = kc * 64;
    bool writer = (jt == 0);

    {   // one-time Whh slice load (transposed)
        int jrow = tid >> 3, kq = (tid & 7) * 8;
        #pragma unroll
        for (int q = 0; q < 8; q++)
            Ws[kq + q][jrow] = Whh[(size_t)(j0 + jrow) * HH + k0 + kq + q];
    }
    for (int i = tid; i < TT; i += 256) cs[i] = g_cnt[i];
    __syncthreads();

    // stage mapping: 2 threads per row (k halves); rows packed low-tid first
    int n = tid >> 1, half = tid & 1;
    int koff = k0 + half * 32;
    // gemm mapping: warp-granular rows so cnt masking retires whole warps
    int w = tid >> 5, lane = tid & 31;
    int nb = w * 16 + (lane & 3) * 4;
    int jb = (lane >> 2) * 4;

    int cntPrev = 0;
    for (int t = 0; t <= TT; t++) {
        int cnt = (t < TT) ? cs[t] : 0;
        int nrows = (t == 0) ? cnt : cntPrev;

        if (n < nrows) {
            const float* src = (t == 0)
                ? (g_h + (size_t)n * HH + koff)
                : (g_xp + (size_t)(t - 1) * NH + (size_t)n * HH + koff);
            #pragma unroll
            for (int q = 0; q < 8; q++) {
                float4 v = __ldcg((const float4*)(src + q * 4));
                if (t > 0) {
                    v.x = tanhf(v.x); v.y = tanhf(v.y);
                    v.z = tanhf(v.z); v.w = tanhf(v.w);
                    if (writer) {
                        *(float4*)&g_h[(size_t)n * HH + koff + q * 4] = v;
                        if (storeOut)
                            *(float4*)&g_out0[(size_t)(t-1) * NH + (size_t)n * HH + koff + q * 4] = v;
                    }
                }
                if (n < cnt) {
                    int kl = half * 32 + q * 4;
                    hs[kl+0][n] = v.x; hs[kl+1][n] = v.y;
                    hs[kl+2][n] = v.z; hs[kl+3][n] = v.w;
                }
            }
        }

        if (cnt == 0) break;        // drain writeback done; uniform exit
        __syncthreads();

        if (nb < cnt) {
            float acc[4][4] = {};
            #pragma unroll 8
            for (int k = 0; k < 64; k++) {
                float4 a4 = *(const float4*)&hs[k][nb];
                float4 b4 = *(const float4*)&Ws[k][jb];
                float av[4] = {a4.x,a4.y,a4.z,a4.w};
                float bv[4] = {b4.x,b4.y,b4.z,b4.w};
                #pragma unroll
                for (int i = 0; i < 4; i++)
                    #pragma unroll
                    for (int j = 0; j < 4; j++)
                        acc[i][j] = fmaf(av[i], bv[j], acc[i][j]);
            }
            float* xpt = g_xp + (size_t)t * NH;
            #pragma unroll
            for (int i = 0; i < 4; i++)
                #pragma unroll
                for (int j = 0; j < 4; j++)
                    atomicAdd(&xpt[(size_t)(nb + i) * HH + j0 + jb + j], acc[i][j]);
        }

        __syncthreads();
        if (tid == 0) {
            __threadfence();
            *(volatile int*)&g_arrive[cta] = t + 1;
        }
        if (tid < RNN_BLOCKS) {
            while (*(volatile int*)&g_arrive[tid] < t + 1) { }
        }
        __threadfence();
        __syncthreads();
        cntPrev = cnt;
    }
}

extern "C" void kernel_launch(void* const* d_in, const int* in_sizes, int n_in,
                              void* d_out, int out_size) {
    const float* x    = (const float*)d_in[0];
    const float* h0   = (const float*)d_in[1];
    const int*   len  = (const int*)  d_in[2];
    const float* Wih0 = (const float*)d_in[3];
    const float* bih0 = (const float*)d_in[4];
    const float* Whh0 = (const float*)d_in[5];
    const float* bhh0 = (const float*)d_in[6];
    const float* Wih1 = (const float*)d_in[7];
    const float* bih1 = (const float*)d_in[8];
    const float* Whh1 = (const float*)d_in[9];
    const float* bhh1 = (const float*)d_in[10];
    const float* Wfc  = (const float*)d_in[11];
    const float* bfc  = (const float*)d_in[12];
    float* out = (float*)d_out;

    count_kernel<<<1, TT>>>(len);

    init_h_kernel<<<NH/256, 256>>>(h0, 0);
    gemm64<<<dim3(HH/128, TT*2), 128>>>(x, 0, Wih0, bih0, bhh0, nullptr, 0, II, HH, 1);
    rnn2<<<RNN_BLOCKS, 256>>>(Whh0, 1);
    copy_h_kernel<<<NH/256, 256>>>(out, 0);

    init_h_kernel<<<NH/256, 256>>>(h0, 1);
    gemm64<<<dim3(HH/128, TT*2), 128>>>(nullptr, 1, Wih1, bih1, bhh1, nullptr, 0, HH, HH, 1);
    rnn2<<<RNN_BLOCKS, 256>>>(Whh1, 0);
    copy_h_kernel<<<NH/256, 256>>>(out, 1);

    gemm64<<<dim3(CC/128, NN/64), 128>>>(nullptr, 2, Wfc, bfc, nullptr, out, 1, HH, CC, 0);
}

// round 9
// speedup vs baseline: 1.2299x; 1.2299x over previous
#include <cuda_runtime.h>
#include <math.h>

#define TT 512
#define NN 128
#define II 256
#define HH 512
#define CC 128
#define NH (NN*HH)
#define RNN_BLOCKS 128
#define H_OFF (NN*CC)

__device__ float g_xp[TT*NN*HH];
__device__ float g_out0[TT*NN*HH];
__device__ float g_h[NH];
__device__ float g_part[8*NH];
__device__ int   g_cnt[TT];
__device__ unsigned g_grp[8];              // 2-level barrier: group counters
__device__ unsigned g_root;                // root counter
__device__ volatile unsigned g_bar_gen;    // generation (monotone)

// ---- grid barrier: PROVEN idiom (R2/R4), hierarchical to cut serialization ----
__device__ __forceinline__ void grid_barrier(unsigned* gen_sh) {
    __syncthreads();
    if (threadIdx.x == 0) {
        unsigned g = *gen_sh;
        int grp = blockIdx.x >> 4;            // 8 groups x 16 CTAs
        __threadfence();
        unsigned p = atomicAdd(&g_grp[grp], 1u);
        if (p == 15u) {                       // last in group
            atomicExch(&g_grp[grp], 0u);
            __threadfence();
            unsigned q = atomicAdd(&g_root, 1u);
            if (q == 7u) {                    // last group
                atomicExch(&g_root, 0u);
                __threadfence();
                g_bar_gen = g + 1u;
            }
        }
        while (g_bar_gen == g) { }            // releaser exits immediately
        *gen_sh = g + 1u;
    }
    __syncthreads();
}

__global__ void count_kernel(const int* __restrict__ len) {
    int t = threadIdx.x, c = 0;
    #pragma unroll 8
    for (int n = 0; n < NN; n++) c += (len[n] > t) ? 1 : 0;
    g_cnt[t] = c;
}

__global__ void init_h_kernel(const float* __restrict__ h0, int layer) {
    int i = blockIdx.x * blockDim.x + threadIdx.x;
    if (i < NH) g_h[i] = h0[layer * NH + i];
}

__global__ void copy_h_kernel(float* __restrict__ dout, int layer) {
    int i = blockIdx.x * blockDim.x + threadIdx.x;
    if (i < NH) dout[H_OFF + layer * NH + i] = g_h[i];
}

// ---- input GEMM + bias: 64x128 tile, 128 thr, 8x8 micro, double-buffered ------
__global__ __launch_bounds__(128)
void gemm64(const float* __restrict__ Aptr, int asel,
            const float* __restrict__ W,
            const float* __restrict__ b1, const float* __restrict__ b2,
            float* __restrict__ Cptr, int csel, int K, int Hout, int useCnt)
{
    const float* A = (asel == 0) ? Aptr : ((asel == 1) ? g_out0 : g_h);
    float* C = (csel == 0) ? g_xp : Cptr;

    int row0;
    if (useCnt) {
        int t = blockIdx.y >> 1, nt = blockIdx.y & 1;
        if (nt * 64 >= g_cnt[t]) return;
        row0 = t * NN + nt * 64;
    } else {
        row0 = blockIdx.y * 64;
    }
    int j0 = blockIdx.x * 128;
    int tid = threadIdx.x;

    __shared__ float As[2][8][68];
    __shared__ float Bs[2][8][132];

    int ar = tid >> 1;
    int ak = (tid & 1) * 4;
    const float* Ap = A + (size_t)(row0 + ar) * K + ak;
    const float* Wp = W + (size_t)(j0 + tid) * K;
    int KT = K >> 3;

    float4 a_r  = *(const float4*)(Ap);
    float4 b_r0 = *(const float4*)(Wp);
    float4 b_r1 = *(const float4*)(Wp + 4);
    As[0][ak+0][ar] = a_r.x; As[0][ak+1][ar] = a_r.y;
    As[0][ak+2][ar] = a_r.z; As[0][ak+3][ar] = a_r.w;
    Bs[0][0][tid] = b_r0.x; Bs[0][1][tid] = b_r0.y;
    Bs[0][2][tid] = b_r0.z; Bs[0][3][tid] = b_r0.w;
    Bs[0][4][tid] = b_r1.x; Bs[0][5][tid] = b_r1.y;
    Bs[0][6][tid] = b_r1.z; Bs[0][7][tid] = b_r1.w;
    __syncthreads();

    int tm = tid & 7;
    int tj = tid >> 3;
    float acc[8][8] = {};

    for (int kt = 0; kt < KT; kt++) {
        int cur = kt & 1;
        bool nxt = (kt + 1 < KT);
        if (nxt) {
            int k0 = (kt + 1) << 3;
            a_r  = *(const float4*)(Ap + k0);
            b_r0 = *(const float4*)(Wp + k0);
            b_r1 = *(const float4*)(Wp + k0 + 4);
        }
        #pragma unroll
        for (int kk = 0; kk < 8; kk++) {
            float4 a0 = *(const float4*)&As[cur][kk][tm*8];
            float4 a1 = *(const float4*)&As[cur][kk][tm*8+4];
            float4 b0 = *(const float4*)&Bs[cur][kk][tj*8];
            float4 b1v= *(const float4*)&Bs[cur][kk][tj*8+4];
            float av[8] = {a0.x,a0.y,a0.z,a0.w,a1.x,a1.y,a1.z,a1.w};
            float bv[8] = {b0.x,b0.y,b0.z,b0.w,b1v.x,b1v.y,b1v.z,b1v.w};
            #pragma unroll
            for (int i = 0; i < 8; i++)
                #pragma unroll
                for (int j = 0; j < 8; j++)
                    acc[i][j] = fmaf(av[i], bv[j], acc[i][j]);
        }
        if (nxt) {
            int nb = cur ^ 1;
            As[nb][ak+0][ar] = a_r.x; As[nb][ak+1][ar] = a_r.y;
            As[nb][ak+2][ar] = a_r.z; As[nb][ak+3][ar] = a_r.w;
            Bs[nb][0][tid] = b_r0.x; Bs[nb][1][tid] = b_r0.y;
            Bs[nb][2][tid] = b_r0.z; Bs[nb][3][tid] = b_r0.w;
            Bs[nb][4][tid] = b_r1.x; Bs[nb][5][tid] = b_r1.y;
            Bs[nb][6][tid] = b_r1.z; Bs[nb][7][tid] = b_r1.w;
        }
        __syncthreads();
    }

    int jc = j0 + tj * 8;
    float bb[8];
    #pragma unroll
    for (int j = 0; j < 8; j++)
        bb[j] = b1[jc+j] + (b2 ? b2[jc+j] : 0.0f);
    #pragma unroll
    for (int i = 0; i < 8; i++) {
        int row = row0 + tm * 8 + i;
        float4 v0 = make_float4(acc[i][0]+bb[0], acc[i][1]+bb[1],
                                acc[i][2]+bb[2], acc[i][3]+bb[3]);
        float4 v1 = make_float4(acc[i][4]+bb[4], acc[i][5]+bb[5],
                                acc[i][6]+bb[6], acc[i][7]+bb[7]);
        *(float4*)(C + (size_t)row * Hout + jc)     = v0;
        *(float4*)(C + (size_t)row * Hout + jc + 4) = v1;
    }
}

// ---- persistent recurrence (R4 dataflow; warp-masked phase1; 2 barriers/step) -
// 128 CTAs = 16 j-tiles(32 cols) x 8 k-chunks(64).
__global__ __launch_bounds__(256)
void rnn_kernel(const float* __restrict__ Whh, int storeOut)
{
    __shared__ float Ws[64][32];
    __shared__ float hs[64][128];
    __shared__ unsigned gen_sh;

    int tid = threadIdx.x, cta = blockIdx.x;
    int jt = cta & 15, kc = cta >> 4;
    int j0 = jt * 32, k0 = kc * 64;

    {   // one-time Whh slice load (transposed)
        int jrow = tid >> 3, kq = (tid & 7) * 8;
        #pragma unroll
        for (int q = 0; q < 8; q++)
            Ws[kq + q][jrow] = Whh[(size_t)(j0 + jrow) * HH + k0 + kq + q];
    }
    if (tid == 0) gen_sh = g_bar_gen;     // pick up current generation
    __syncthreads();

    int n = tid & 127, half = tid >> 7;   // stage: 2 threads per row
    int w = tid >> 5, lane = tid & 31;    // phase1: warp w owns rows [w*16, w*16+16)
    int nb = w * 16 + (lane & 3) * 4;
    int jb = (lane >> 2) * 4;

    for (int t = 0; t < TT; t++) {
        int cnt = g_cnt[t];
        if (cnt == 0) break;              // uniform (cnt monotone non-increasing)

        // stage h^T for our k-chunk, active rows only (cross-CTA -> bypass L1)
        if (n < cnt) {
            #pragma unroll
            for (int q = 0; q < 8; q++) {
                int kl = half * 32 + q * 4;
                float4 v = __ldcg((const float4*)&g_h[n * HH + k0 + kl]);
                hs[kl+0][n] = v.x; hs[kl+1][n] = v.y;
                hs[kl+2][n] = v.z; hs[kl+3][n] = v.w;
            }
        }
        __syncthreads();

        if (nb < cnt) {                   // whole warp skips when cnt <= w*16
            float acc[4][4] = {};
            #pragma unroll 8
            for (int k = 0; k < 64; k++) {
                float4 a4 = *(const float4*)&hs[k][nb];
                float4 b4 = *(const float4*)&Ws[k][jb];
                float av[4] = {a4.x,a4.y,a4.z,a4.w};
                float bv[4] = {b4.x,b4.y,b4.z,b4.w};
                #pragma unroll
                for (int i = 0; i < 4; i++)
                    #pragma unroll
                    for (int j = 0; j < 4; j++)
                        acc[i][j] = fmaf(av[i], bv[j], acc[i][j]);
            }
            #pragma unroll
            for (int i = 0; i < 4; i++)
                *(float4*)&g_part[(size_t)kc * NH + (nb + i) * HH + j0 + jb] =
                    make_float4(acc[i][0], acc[i][1], acc[i][2], acc[i][3]);
        }

        grid_barrier(&gen_sh);

        {   // phase 2: reduce partials + xproj, tanh, update h
            const float* xpt = g_xp + (size_t)t * NH;
            float* outt = g_out0 + (size_t)t * NH;
            int total = cnt * HH;
            for (int idx = cta * 256 + tid; idx < total; idx += RNN_BLOCKS * 256) {
                float s = xpt[idx];
                #pragma unroll
                for (int p = 0; p < 8; p++)
                    s += __ldcg(&g_part[p * NH + idx]);
                float v = tanhf(s);
                g_h[idx] = v;
                if (storeOut) outt[idx] = v;
            }
        }

        grid_barrier(&gen_sh);
    }
}

extern "C" void kernel_launch(void* const* d_in, const int* in_sizes, int n_in,
                              void* d_out, int out_size) {
    const float* x    = (const float*)d_in[0];
    const float* h0   = (const float*)d_in[1];
    const int*   len  = (const int*)  d_in[2];
    const float* Wih0 = (const float*)d_in[3];
    const float* bih0 = (const float*)d_in[4];
    const float* Whh0 = (const float*)d_in[5];
    const float* bhh0 = (const float*)d_in[6];
    const float* Wih1 = (const float*)d_in[7];
    const float* bih1 = (const float*)d_in[8];
    const float* Whh1 = (const float*)d_in[9];
    const float* bhh1 = (const float*)d_in[10];
    const float* Wfc  = (const float*)d_in[11];
    const float* bfc  = (const float*)d_in[12];
    float* out = (float*)d_out;

    count_kernel<<<1, TT>>>(len);

    init_h_kernel<<<NH/256, 256>>>(h0, 0);
    gemm64<<<dim3(HH/128, TT*2), 128>>>(x, 0, Wih0, bih0, bhh0, nullptr, 0, II, HH, 1);
    rnn_kernel<<<RNN_BLOCKS, 256>>>(Whh0, 1);
    copy_h_kernel<<<NH/256, 256>>>(out, 0);

    init_h_kernel<<<NH/256, 256>>>(h0, 1);
    gemm64<<<dim3(HH/128, TT*2), 128>>>(nullptr, 1, Wih1, bih1, bhh1, nullptr, 0, HH, HH, 1);
    rnn_kernel<<<RNN_BLOCKS, 256>>>(Whh1, 0);
    copy_h_kernel<<<NH/256, 256>>>(out, 1);

    gemm64<<<dim3(CC/128, NN/64), 128>>>(nullptr, 2, Wfc, bfc, nullptr, out, 1, HH, CC, 0);
}

// round 10
// speedup vs baseline: 1.4677x; 1.1933x over previous
#include <cuda_runtime.h>
#include <math.h>

#define TT 512
#define NN 128
#define II 256
#define HH 512
#define CC 128
#define NH (NN*HH)
#define RNN_BLOCKS 128
#define H_OFF (NN*CC)

__device__ float g_xp[TT*NN*HH];
__device__ float g_out0[TT*NN*HH];
__device__ float g_h[NH];
__device__ float g_part[8*NH];
__device__ int   g_cnt[TT];
__device__ unsigned g_bar_count;
__device__ volatile unsigned g_bar_gen;

// ---- grid barrier: PROVEN flat idiom (R2/R4) -----------------------------------
__device__ __forceinline__ void grid_barrier(unsigned* gen_sh, int nblk) {
    __syncthreads();
    if (threadIdx.x == 0) {
        unsigned g = *gen_sh;
        __threadfence();
        unsigned prev = atomicAdd(&g_bar_count, 1u);
        if (prev == (unsigned)(nblk - 1)) {
            g_bar_count = 0u;
            __threadfence();
            g_bar_gen = g + 1u;
        } else {
            while (g_bar_gen == g) { }
        }
        *gen_sh = g + 1u;
    }
    __syncthreads();
}

__global__ void count_kernel(const int* __restrict__ len) {
    int t = threadIdx.x, c = 0;
    #pragma unroll 8
    for (int n = 0; n < NN; n++) c += (len[n] > t) ? 1 : 0;
    g_cnt[t] = c;
}

__global__ void init_h_kernel(const float* __restrict__ h0, int layer) {
    int i = blockIdx.x * blockDim.x + threadIdx.x;
    if (i < NH) g_h[i] = h0[layer * NH + i];
}

__global__ void copy_h_kernel(float* __restrict__ dout, int layer) {
    int i = blockIdx.x * blockDim.x + threadIdx.x;
    if (i < NH) dout[H_OFF + layer * NH + i] = g_h[i];
}

// ---- input GEMM + bias: 64x128 tile, 128 thr, 8x8 micro, double-buffered ------
__global__ __launch_bounds__(128)
void gemm64(const float* __restrict__ Aptr, int asel,
            const float* __restrict__ W,
            const float* __restrict__ b1, const float* __restrict__ b2,
            float* __restrict__ Cptr, int csel, int K, int Hout, int useCnt)
{
    const float* A = (asel == 0) ? Aptr : ((asel == 1) ? g_out0 : g_h);
    float* C = (csel == 0) ? g_xp : Cptr;

    int row0;
    if (useCnt) {
        int t = blockIdx.y >> 1, nt = blockIdx.y & 1;
        if (nt * 64 >= g_cnt[t]) return;
        row0 = t * NN + nt * 64;
    } else {
        row0 = blockIdx.y * 64;
    }
    int j0 = blockIdx.x * 128;
    int tid = threadIdx.x;

    __shared__ float As[2][8][68];
    __shared__ float Bs[2][8][132];

    int ar = tid >> 1;
    int ak = (tid & 1) * 4;
    const float* Ap = A + (size_t)(row0 + ar) * K + ak;
    const float* Wp = W + (size_t)(j0 + tid) * K;
    int KT = K >> 3;

    float4 a_r  = *(const float4*)(Ap);
    float4 b_r0 = *(const float4*)(Wp);
    float4 b_r1 = *(const float4*)(Wp + 4);
    As[0][ak+0][ar] = a_r.x; As[0][ak+1][ar] = a_r.y;
    As[0][ak+2][ar] = a_r.z; As[0][ak+3][ar] = a_r.w;
    Bs[0][0][tid] = b_r0.x; Bs[0][1][tid] = b_r0.y;
    Bs[0][2][tid] = b_r0.z; Bs[0][3][tid] = b_r0.w;
    Bs[0][4][tid] = b_r1.x; Bs[0][5][tid] = b_r1.y;
    Bs[0][6][tid] = b_r1.z; Bs[0][7][tid] = b_r1.w;
    __syncthreads();

    int tm = tid & 7;
    int tj = tid >> 3;
    float acc[8][8] = {};

    for (int kt = 0; kt < KT; kt++) {
        int cur = kt & 1;
        bool nxt = (kt + 1 < KT);
        if (nxt) {
            int k0 = (kt + 1) << 3;
            a_r  = *(const float4*)(Ap + k0);
            b_r0 = *(const float4*)(Wp + k0);
            b_r1 = *(const float4*)(Wp + k0 + 4);
        }
        #pragma unroll
        for (int kk = 0; kk < 8; kk++) {
            float4 a0 = *(const float4*)&As[cur][kk][tm*8];
            float4 a1 = *(const float4*)&As[cur][kk][tm*8+4];
            float4 b0 = *(const float4*)&Bs[cur][kk][tj*8];
            float4 b1v= *(const float4*)&Bs[cur][kk][tj*8+4];
            float av[8] = {a0.x,a0.y,a0.z,a0.w,a1.x,a1.y,a1.z,a1.w};
            float bv[8] = {b0.x,b0.y,b0.z,b0.w,b1v.x,b1v.y,b1v.z,b1v.w};
            #pragma unroll
            for (int i = 0; i < 8; i++)
                #pragma unroll
                for (int j = 0; j < 8; j++)
                    acc[i][j] = fmaf(av[i], bv[j], acc[i][j]);
        }
        if (nxt) {
            int nb = cur ^ 1;
            As[nb][ak+0][ar] = a_r.x; As[nb][ak+1][ar] = a_r.y;
            As[nb][ak+2][ar] = a_r.z; As[nb][ak+3][ar] = a_r.w;
            Bs[nb][0][tid] = b_r0.x; Bs[nb][1][tid] = b_r0.y;
            Bs[nb][2][tid] = b_r0.z; Bs[nb][3][tid] = b_r0.w;
            Bs[nb][4][tid] = b_r1.x; Bs[nb][5][tid] = b_r1.y;
            Bs[nb][6][tid] = b_r1.z; Bs[nb][7][tid] = b_r1.w;
        }
        __syncthreads();
    }

    int jc = j0 + tj * 8;
    float bb[8];
    #pragma unroll
    for (int j = 0; j < 8; j++)
        bb[j] = b1[jc+j] + (b2 ? b2[jc+j] : 0.0f);
    #pragma unroll
    for (int i = 0; i < 8; i++) {
        int row = row0 + tm * 8 + i;
        float4 v0 = make_float4(acc[i][0]+bb[0], acc[i][1]+bb[1],
                                acc[i][2]+bb[2], acc[i][3]+bb[3]);
        float4 v1 = make_float4(acc[i][4]+bb[4], acc[i][5]+bb[5],
                                acc[i][6]+bb[6], acc[i][7]+bb[7]);
        *(float4*)(C + (size_t)row * Hout + jc)     = v0;
        *(float4*)(C + (size_t)row * Hout + jc + 4) = v1;
    }
}

// ---- persistent recurrence: R4 dataflow + warp-granular phase1 masking --------
// 128 CTAs = 16 j-tiles(32 cols) x 8 k-chunks(64). Two phases, 2 barriers/step.
__global__ __launch_bounds__(256)
void rnn_kernel(const float* __restrict__ Whh, int storeOut)
{
    __shared__ float Ws[64][32];
    __shared__ float hs[64][128];
    __shared__ unsigned gen_sh;

    int tid = threadIdx.x, cta = blockIdx.x;
    int jt = cta & 15, kc = cta >> 4;
    int j0 = jt * 32, k0 = kc * 64;

    {   // one-time Whh slice load (transposed)
        int jrow = tid >> 3, kq = (tid & 7) * 8;
        #pragma unroll
        for (int q = 0; q < 8; q++)
            Ws[kq + q][jrow] = Whh[(size_t)(j0 + jrow) * HH + k0 + kq + q];
    }
    if (tid == 0) gen_sh = g_bar_gen;
    __syncthreads();

    int n = tid & 127, half = tid >> 7;   // stage: 2 threads per row
    int w = tid >> 5, lane = tid & 31;    // phase1: warp w owns rows [w*16, w*16+16)
    int nb = w * 16 + (lane & 3) * 4;
    int jb = (lane >> 2) * 4;

    for (int t = 0; t < TT; t++) {
        int cnt = g_cnt[t];
        if (cnt == 0) break;

        // stage h^T for our k-chunk, active rows only (cross-CTA -> bypass L1)
        if (n < cnt) {
            #pragma unroll
            for (int q = 0; q < 8; q++) {
                int kl = half * 32 + q * 4;
                float4 v = __ldcg((const float4*)&g_h[n * HH + k0 + kl]);
                hs[kl+0][n] = v.x; hs[kl+1][n] = v.y;
                hs[kl+2][n] = v.z; hs[kl+3][n] = v.w;
            }
        }
        __syncthreads();

        if (nb < cnt) {                   // whole warp retires when cnt <= w*16
            float acc[4][4] = {};
            #pragma unroll 8
            for (int k = 0; k < 64; k++) {
                float4 a4 = *(const float4*)&hs[k][nb];
                float4 b4 = *(const float4*)&Ws[k][jb];
                float av[4] = {a4.x,a4.y,a4.z,a4.w};
                float bv[4] = {b4.x,b4.y,b4.z,b4.w};
                #pragma unroll
                for (int i = 0; i < 4; i++)
                    #pragma unroll
                    for (int j = 0; j < 4; j++)
                        acc[i][j] = fmaf(av[i], bv[j], acc[i][j]);
            }
            #pragma unroll
            for (int i = 0; i < 4; i++)
                *(float4*)&g_part[(size_t)kc * NH + (nb + i) * HH + j0 + jb] =
                    make_float4(acc[i][0], acc[i][1], acc[i][2], acc[i][3]);
        }

        grid_barrier(&gen_sh, RNN_BLOCKS);

        {   // phase 2: reduce partials + xproj, tanh, update h
            const float* xpt = g_xp + (size_t)t * NH;
            float* outt = g_out0 + (size_t)t * NH;
            int total = cnt * HH;
            for (int idx = cta * 256 + tid; idx < total; idx += RNN_BLOCKS * 256) {
                float s = xpt[idx];
                #pragma unroll
                for (int p = 0; p < 8; p++)
                    s += __ldcg(&g_part[p * NH + idx]);
                float v = tanhf(s);
                g_h[idx] = v;
                if (storeOut) outt[idx] = v;
            }
        }

        grid_barrier(&gen_sh, RNN_BLOCKS);
    }
}

extern "C" void kernel_launch(void* const* d_in, const int* in_sizes, int n_in,
                              void* d_out, int out_size) {
    const float* x    = (const float*)d_in[0];
    const float* h0   = (const float*)d_in[1];
    const int*   len  = (const int*)  d_in[2];
    const float* Wih0 = (const float*)d_in[3];
    const float* bih0 = (const float*)d_in[4];
    const float* Whh0 = (const float*)d_in[5];
    const float* bhh0 = (const float*)d_in[6];
    const float* Wih1 = (const float*)d_in[7];
    const float* bih1 = (const float*)d_in[8];
    const float* Whh1 = (const float*)d_in[9];
    const float* bhh1 = (const float*)d_in[10];
    const float* Wfc  = (const float*)d_in[11];
    const float* bfc  = (const float*)d_in[12];
    float* out = (float*)d_out;

    count_kernel<<<1, TT>>>(len);

    init_h_kernel<<<NH/256, 256>>>(h0, 0);
    gemm64<<<dim3(HH/128, TT*2), 128>>>(x, 0, Wih0, bih0, bhh0, nullptr, 0, II, HH, 1);
    rnn_kernel<<<RNN_BLOCKS, 256>>>(Whh0, 1);
    copy_h_kernel<<<NH/256, 256>>>(out, 0);

    init_h_kernel<<<NH/256, 256>>>(h0, 1);
    gemm64<<<dim3(HH/128, TT*2), 128>>>(nullptr, 1, Wih1, bih1, bhh1, nullptr, 0, HH, HH, 1);
    rnn_kernel<<<RNN_BLOCKS, 256>>>(Whh1, 0);
    copy_h_kernel<<<NH/256, 256>>>(out, 1);

    gemm64<<<dim3(CC/128, NN/64), 128>>>(nullptr, 2, Wfc, bfc, nullptr, out, 1, HH, CC, 0);
}

// round 11
// speedup vs baseline: 1.8333x; 1.2491x over previous
#include <cuda_runtime.h>
#include <math.h>

#define TT 512
#define NN 128
#define II 256
#define HH 512
#define CC 128
#define NH (NN*HH)
#define RNN_BLOCKS 128
#define H_OFF (NN*CC)

__device__ float g_xp[TT*NN*HH];      // layer-0 xproj (+both biases)
__device__ float g_h0[NH];            // layer-0 hidden
__device__ float g_h1[NH];            // layer-1 hidden
__device__ float g_part0[8*NH];       // k-split partials, layer 0
__device__ float g_part1[8*NH];       // k-split partials, layer 1
__device__ int   g_cnt[TT];
__device__ unsigned g_bar_count;
__device__ volatile unsigned g_bar_gen;

// ---- grid barrier: PROVEN flat idiom (R2/R4/R10) -------------------------------
__device__ __forceinline__ void grid_barrier(unsigned* gen_sh, int nblk) {
    __syncthreads();
    if (threadIdx.x == 0) {
        unsigned g = *gen_sh;
        __threadfence();
        unsigned prev = atomicAdd(&g_bar_count, 1u);
        if (prev == (unsigned)(nblk - 1)) {
            g_bar_count = 0u;
            __threadfence();
            g_bar_gen = g + 1u;
        } else {
            while (g_bar_gen == g) { }
        }
        *gen_sh = g + 1u;
    }
    __syncthreads();
}

__global__ void count_kernel(const int* __restrict__ len) {
    int t = threadIdx.x, c = 0;
    #pragma unroll 8
    for (int n = 0; n < NN; n++) c += (len[n] > t) ? 1 : 0;
    g_cnt[t] = c;
}

__global__ void init_h_kernel(const float* __restrict__ h0) {
    int i = blockIdx.x * blockDim.x + threadIdx.x;
    if (i < NH) { g_h0[i] = h0[i]; g_h1[i] = h0[NH + i]; }
}

__global__ void copy_h_kernel(float* __restrict__ dout) {
    int i = blockIdx.x * blockDim.x + threadIdx.x;
    if (i < NH) {
        dout[H_OFF + i]      = g_h0[i];
        dout[H_OFF + NH + i] = g_h1[i];
    }
}

// ---- input GEMM + bias: 64x128 tile, 128 thr, 8x8 micro, double-buffered ------
// asel: 0=Aptr, 1=g_h1. csel: 0=g_xp, 1=Cptr.
__global__ __launch_bounds__(128)
void gemm64(const float* __restrict__ Aptr, int asel,
            const float* __restrict__ W,
            const float* __restrict__ b1, const float* __restrict__ b2,
            float* __restrict__ Cptr, int csel, int K, int Hout, int useCnt)
{
    const float* A = (asel == 0) ? Aptr : g_h1;
    float* C = (csel == 0) ? g_xp : Cptr;

    int row0;
    if (useCnt) {
        int t = blockIdx.y >> 1, nt = blockIdx.y & 1;
        if (nt * 64 >= g_cnt[t]) return;
        row0 = t * NN + nt * 64;
    } else {
        row0 = blockIdx.y * 64;
    }
    int j0 = blockIdx.x * 128;
    int tid = threadIdx.x;

    __shared__ float As[2][8][68];
    __shared__ float Bs[2][8][132];

    int ar = tid >> 1;
    int ak = (tid & 1) * 4;
    const float* Ap = A + (size_t)(row0 + ar) * K + ak;
    const float* Wp = W + (size_t)(j0 + tid) * K;
    int KT = K >> 3;

    float4 a_r  = *(const float4*)(Ap);
    float4 b_r0 = *(const float4*)(Wp);
    float4 b_r1 = *(const float4*)(Wp + 4);
    As[0][ak+0][ar] = a_r.x; As[0][ak+1][ar] = a_r.y;
    As[0][ak+2][ar] = a_r.z; As[0][ak+3][ar] = a_r.w;
    Bs[0][0][tid] = b_r0.x; Bs[0][1][tid] = b_r0.y;
    Bs[0][2][tid] = b_r0.z; Bs[0][3][tid] = b_r0.w;
    Bs[0][4][tid] = b_r1.x; Bs[0][5][tid] = b_r1.y;
    Bs[0][6][tid] = b_r1.z; Bs[0][7][tid] = b_r1.w;
    __syncthreads();

    int tm = tid & 7;
    int tj = tid >> 3;
    float acc[8][8] = {};

    for (int kt = 0; kt < KT; kt++) {
        int cur = kt & 1;
        bool nxt = (kt + 1 < KT);
        if (nxt) {
            int k0 = (kt + 1) << 3;
            a_r  = *(const float4*)(Ap + k0);
            b_r0 = *(const float4*)(Wp + k0);
            b_r1 = *(const float4*)(Wp + k0 + 4);
        }
        #pragma unroll
        for (int kk = 0; kk < 8; kk++) {
            float4 a0 = *(const float4*)&As[cur][kk][tm*8];
            float4 a1 = *(const float4*)&As[cur][kk][tm*8+4];
            float4 b0 = *(const float4*)&Bs[cur][kk][tj*8];
            float4 b1v= *(const float4*)&Bs[cur][kk][tj*8+4];
            float av[8] = {a0.x,a0.y,a0.z,a0.w,a1.x,a1.y,a1.z,a1.w};
            float bv[8] = {b0.x,b0.y,b0.z,b0.w,b1v.x,b1v.y,b1v.z,b1v.w};
            #pragma unroll
            for (int i = 0; i < 8; i++)
                #pragma unroll
                for (int j = 0; j < 8; j++)
                    acc[i][j] = fmaf(av[i], bv[j], acc[i][j]);
        }
        if (nxt) {
            int nb = cur ^ 1;
            As[nb][ak+0][ar] = a_r.x; As[nb][ak+1][ar] = a_r.y;
            As[nb][ak+2][ar] = a_r.z; As[nb][ak+3][ar] = a_r.w;
            Bs[nb][0][tid] = b_r0.x; Bs[nb][1][tid] = b_r0.y;
            Bs[nb][2][tid] = b_r0.z; Bs[nb][3][tid] = b_r0.w;
            Bs[nb][4][tid] = b_r1.x; Bs[nb][5][tid] = b_r1.y;
            Bs[nb][6][tid] = b_r1.z; Bs[nb][7][tid] = b_r1.w;
        }
        __syncthreads();
    }

    int jc = j0 + tj * 8;
    float bb[8];
    #pragma unroll
    for (int j = 0; j < 8; j++)
        bb[j] = b1[jc+j] + (b2 ? b2[jc+j] : 0.0f);
    #pragma unroll
    for (int i = 0; i < 8; i++) {
        int row = row0 + tm * 8 + i;
        float4 v0 = make_float4(acc[i][0]+bb[0], acc[i][1]+bb[1],
                                acc[i][2]+bb[2], acc[i][3]+bb[3]);
        float4 v1 = make_float4(acc[i][4]+bb[4], acc[i][5]+bb[5],
                                acc[i][6]+bb[6], acc[i][7]+bb[7]);
        *(float4*)(C + (size_t)row * Hout + jc)     = v0;
        *(float4*)(C + (size_t)row * Hout + jc + 4) = v1;
    }
}

// ---- fused 2-layer wavefront recurrence ----------------------------------------
// Superstep s: layer0 computes h0(s) [needs h0(s-1), xp0[s]];
//              layer1 computes h1(s-1) [needs h1(s-2), out0(s-1)=g_h0].
// 128 CTAs = 16 j-tiles(32 cols) x 8 k-chunks(64). Same 2-phase/2-barrier
// protocol as R10; per-CTA work = 3 GEMM slices (Whh0 | Whh1 | Wih1).
__global__ __launch_bounds__(256)
void rnn5(const float* __restrict__ Whh0, const float* __restrict__ Whh1,
          const float* __restrict__ Wih1,
          const float* __restrict__ bih1, const float* __restrict__ bhh1)
{
    extern __shared__ float sm[];
    float* Ws0  = sm;               // [64][32]
    float* Wsh1 = sm + 2048;        // [64][32]
    float* Wsi1 = sm + 4096;        // [64][32]
    float* hs0  = sm + 6144;        // [64][128]
    float* hs1  = sm + 14336;       // [64][128]
    float* b1s  = sm + 22528;       // [512]
    int*   cs   = (int*)(sm + 23040); // [512]
    __shared__ unsigned gen_sh;

    int tid = threadIdx.x, cta = blockIdx.x;
    int jt = cta & 15, kc = cta >> 4;
    int j0 = jt * 32, k0 = kc * 64;

    {   // one-time weight slice loads (transposed: Ws[k][j])
        int jrow = tid >> 3, kq = (tid & 7) * 8;
        #pragma unroll
        for (int q = 0; q < 8; q++) {
            size_t widx = (size_t)(j0 + jrow) * HH + k0 + kq + q;
            int sidx = (kq + q) * 32 + jrow;
            Ws0[sidx]  = Whh0[widx];
            Wsh1[sidx] = Whh1[widx];
            Wsi1[sidx] = Wih1[widx];
        }
    }
    for (int i = tid; i < HH; i += 256) b1s[i] = bih1[i] + bhh1[i];
    for (int i = tid; i < TT; i += 256) cs[i] = g_cnt[i];
    if (tid == 0) gen_sh = g_bar_gen;
    __syncthreads();

    int n = tid & 127, half = tid >> 7;   // stage: 2 threads per row
    int w = tid >> 5, lane = tid & 31;    // gemm: warp w owns rows [w*16, w*16+16)
    int nb = w * 16 + (lane & 3) * 4;
    int jb = (lane >> 2) * 4;

    for (int s = 0; s <= TT; s++) {
        int cnt0 = (s < TT) ? cs[s] : 0;
        int cnt1 = (s > 0) ? cs[s - 1] : 0;
        int sb = max(cnt0, cnt1);
        if (sb == 0) break;

        // ---- stage h slices for our k-chunk (cross-CTA -> bypass L1) ----
        if (n < sb) {
            const float* src = g_h0 + (size_t)n * HH + k0 + half * 32;
            #pragma unroll
            for (int q = 0; q < 8; q++) {
                float4 v = __ldcg((const float4*)(src + q * 4));
                int kl = half * 32 + q * 4;
                hs0[(kl+0)*128 + n] = v.x; hs0[(kl+1)*128 + n] = v.y;
                hs0[(kl+2)*128 + n] = v.z; hs0[(kl+3)*128 + n] = v.w;
            }
        }
        if (n < cnt1) {
            const float* src = g_h1 + (size_t)n * HH + k0 + half * 32;
            #pragma unroll
            for (int q = 0; q < 8; q++) {
                float4 v = __ldcg((const float4*)(src + q * 4));
                int kl = half * 32 + q * 4;
                hs1[(kl+0)*128 + n] = v.x; hs1[(kl+1)*128 + n] = v.y;
                hs1[(kl+2)*128 + n] = v.z; hs1[(kl+3)*128 + n] = v.w;
            }
        }
        __syncthreads();

        // ---- phase 1: partial GEMMs ----
        if (nb < cnt0) {   // layer 0: h0prev @ Whh0
            float acc[4][4] = {};
            #pragma unroll 8
            for (int k = 0; k < 64; k++) {
                float4 a4 = *(const float4*)&hs0[k*128 + nb];
                float4 b4 = *(const float4*)&Ws0[k*32 + jb];
                float av[4] = {a4.x,a4.y,a4.z,a4.w};
                float bv[4] = {b4.x,b4.y,b4.z,b4.w};
                #pragma unroll
                for (int i = 0; i < 4; i++)
                    #pragma unroll
                    for (int j = 0; j < 4; j++)
                        acc[i][j] = fmaf(av[i], bv[j], acc[i][j]);
            }
            #pragma unroll
            for (int i = 0; i < 4; i++)
                *(float4*)&g_part0[(size_t)kc * NH + (nb + i) * HH + j0 + jb] =
                    make_float4(acc[i][0], acc[i][1], acc[i][2], acc[i][3]);
        }
        if (nb < cnt1) {   // layer 1: h1prev @ Whh1 + out0prev @ Wih1
            float acc[4][4] = {};
            #pragma unroll 8
            for (int k = 0; k < 64; k++) {
                float4 a4 = *(const float4*)&hs1[k*128 + nb];
                float4 b4 = *(const float4*)&Wsh1[k*32 + jb];
                float av[4] = {a4.x,a4.y,a4.z,a4.w};
                float bv[4] = {b4.x,b4.y,b4.z,b4.w};
                #pragma unroll
                for (int i = 0; i < 4; i++)
                    #pragma unroll
                    for (int j = 0; j < 4; j++)
                        acc[i][j] = fmaf(av[i], bv[j], acc[i][j]);
            }
            #pragma unroll 8
            for (int k = 0; k < 64; k++) {
                float4 a4 = *(const float4*)&hs0[k*128 + nb];
                float4 b4 = *(const float4*)&Wsi1[k*32 + jb];
                float av[4] = {a4.x,a4.y,a4.z,a4.w};
                float bv[4] = {b4.x,b4.y,b4.z,b4.w};
                #pragma unroll
                for (int i = 0; i < 4; i++)
                    #pragma unroll
                    for (int j = 0; j < 4; j++)
                        acc[i][j] = fmaf(av[i], bv[j], acc[i][j]);
            }
            #pragma unroll
            for (int i = 0; i < 4; i++)
                *(float4*)&g_part1[(size_t)kc * NH + (nb + i) * HH + j0 + jb] =
                    make_float4(acc[i][0], acc[i][1], acc[i][2], acc[i][3]);
        }

        grid_barrier(&gen_sh, RNN_BLOCKS);

        // ---- phase 2: reduce + tanh + h updates ----
        if (cnt0 > 0) {
            const float* xpt = g_xp + (size_t)s * NH;
            int total = cnt0 * HH;
            for (int idx = cta * 256 + tid; idx < total; idx += RNN_BLOCKS * 256) {
                float v = xpt[idx];
                #pragma unroll
                for (int p = 0; p < 8; p++)
                    v += __ldcg(&g_part0[p * NH + idx]);
                g_h0[idx] = tanhf(v);
            }
        }
        if (cnt1 > 0) {
            int total = cnt1 * HH;
            for (int idx = cta * 256 + tid; idx < total; idx += RNN_BLOCKS * 256) {
                float v = b1s[idx & (HH - 1)];
                #pragma unroll
                for (int p = 0; p < 8; p++)
                    v += __ldcg(&g_part1[p * NH + idx]);
                g_h1[idx] = tanhf(v);
            }
        }

        grid_barrier(&gen_sh, RNN_BLOCKS);
    }
}

extern "C" void kernel_launch(void* const* d_in, const int* in_sizes, int n_in,
                              void* d_out, int out_size) {
    const float* x    = (const float*)d_in[0];
    const float* h0   = (const float*)d_in[1];
    const int*   len  = (const int*)  d_in[2];
    const float* Wih0 = (const float*)d_in[3];
    const float* bih0 = (const float*)d_in[4];
    const float* Whh0 = (const float*)d_in[5];
    const float* bhh0 = (const float*)d_in[6];
    const float* Wih1 = (const float*)d_in[7];
    const float* bih1 = (const float*)d_in[8];
    const float* Whh1 = (const float*)d_in[9];
    const float* bhh1 = (const float*)d_in[10];
    const float* Wfc  = (const float*)d_in[11];
    const float* bfc  = (const float*)d_in[12];
    float* out = (float*)d_out;

    const int SMEM = 23552 * 4;   // 94208 B dynamic
    static int smem_set = 0;
    if (!smem_set) {
        cudaFuncSetAttribute(rnn5, cudaFuncAttributeMaxDynamicSharedMemorySize, SMEM);
        smem_set = 1;
    }

    count_kernel<<<1, TT>>>(len);
    init_h_kernel<<<NH/256, 256>>>(h0);

    // layer-0 xproj (+ both layer-0 biases)
    gemm64<<<dim3(HH/128, TT*2), 128>>>(x, 0, Wih0, bih0, bhh0, nullptr, 0, II, HH, 1);

    // fused 2-layer wavefront recurrence
    rnn5<<<RNN_BLOCKS, 256, SMEM>>>(Whh0, Whh1, Wih1, bih1, bhh1);

    copy_h_kernel<<<NH/256, 256>>>(out);

    // logits = h1_final @ Wfc^T + bfc
    gemm64<<<dim3(CC/128, NN/64), 128>>>(nullptr, 1, Wfc, bfc, nullptr, out, 1, HH, CC, 0);
}

// round 12
// speedup vs baseline: 2.3906x; 1.3040x over previous
#include <cuda_runtime.h>
#include <cuda_bf16.h>
#include <math.h>

#define TT 512
#define NN 128
#define II 256
#define HH 512
#define CC 128
#define NH (NN*HH)
#define RNN_BLOCKS 128
#define H_OFF (NN*CC)

__device__ float g_xp[TT*NN*HH];      // layer-0 xproj (+both layer-0 biases)
__device__ float g_h0[NH];            // layer-0 hidden (fp32 master)
__device__ float g_h1[NH];            // layer-1 hidden (fp32 master)
__device__ float g_part0[8*NH];       // k-split partials, layer 0
__device__ float g_part1[8*NH];       // k-split partials, layer 1
__device__ int   g_cnt[TT];
__device__ unsigned g_bar_count;
__device__ volatile unsigned g_bar_gen;

// ---- grid barrier: PROVEN flat idiom (R2/R4/R10/R11) ---------------------------
__device__ __forceinline__ void grid_barrier(unsigned* gen_sh, int nblk) {
    __syncthreads();
    if (threadIdx.x == 0) {
        unsigned g = *gen_sh;
        __threadfence();
        unsigned prev = atomicAdd(&g_bar_count, 1u);
        if (prev == (unsigned)(nblk - 1)) {
            g_bar_count = 0u;
            __threadfence();
            g_bar_gen = g + 1u;
        } else {
            while (g_bar_gen == g) { }
        }
        *gen_sh = g + 1u;
    }
    __syncthreads();
}

__global__ void count_kernel(const int* __restrict__ len) {
    int t = threadIdx.x, c = 0;
    #pragma unroll 8
    for (int n = 0; n < NN; n++) c += (len[n] > t) ? 1 : 0;
    g_cnt[t] = c;
}

__global__ void init_h_kernel(const float* __restrict__ h0) {
    int i = blockIdx.x * blockDim.x + threadIdx.x;
    if (i < NH) { g_h0[i] = h0[i]; g_h1[i] = h0[NH + i]; }
}

__global__ void copy_h_kernel(float* __restrict__ dout) {
    int i = blockIdx.x * blockDim.x + threadIdx.x;
    if (i < NH) {
        dout[H_OFF + i]      = g_h0[i];
        dout[H_OFF + NH + i] = g_h1[i];
    }
}

// ---- input GEMM + bias (unchanged, proven): 64x128 tile fp32 -------------------
__global__ __launch_bounds__(128)
void gemm64(const float* __restrict__ Aptr, int asel,
            const float* __restrict__ W,
            const float* __restrict__ b1, const float* __restrict__ b2,
            float* __restrict__ Cptr, int csel, int K, int Hout, int useCnt)
{
    const float* A = (asel == 0) ? Aptr : g_h1;
    float* C = (csel == 0) ? g_xp : Cptr;

    int row0;
    if (useCnt) {
        int t = blockIdx.y >> 1, nt = blockIdx.y & 1;
        if (nt * 64 >= g_cnt[t]) return;
        row0 = t * NN + nt * 64;
    } else {
        row0 = blockIdx.y * 64;
    }
    int j0 = blockIdx.x * 128;
    int tid = threadIdx.x;

    __shared__ float As[2][8][68];
    __shared__ float Bs[2][8][132];

    int ar = tid >> 1;
    int ak = (tid & 1) * 4;
    const float* Ap = A + (size_t)(row0 + ar) * K + ak;
    const float* Wp = W + (size_t)(j0 + tid) * K;
    int KT = K >> 3;

    float4 a_r  = *(const float4*)(Ap);
    float4 b_r0 = *(const float4*)(Wp);
    float4 b_r1 = *(const float4*)(Wp + 4);
    As[0][ak+0][ar] = a_r.x; As[0][ak+1][ar] = a_r.y;
    As[0][ak+2][ar] = a_r.z; As[0][ak+3][ar] = a_r.w;
    Bs[0][0][tid] = b_r0.x; Bs[0][1][tid] = b_r0.y;
    Bs[0][2][tid] = b_r0.z; Bs[0][3][tid] = b_r0.w;
    Bs[0][4][tid] = b_r1.x; Bs[0][5][tid] = b_r1.y;
    Bs[0][6][tid] = b_r1.z; Bs[0][7][tid] = b_r1.w;
    __syncthreads();

    int tm = tid & 7;
    int tj = tid >> 3;
    float acc[8][8] = {};

    for (int kt = 0; kt < KT; kt++) {
        int cur = kt & 1;
        bool nxt = (kt + 1 < KT);
        if (nxt) {
            int k0 = (kt + 1) << 3;
            a_r  = *(const float4*)(Ap + k0);
            b_r0 = *(const float4*)(Wp + k0);
            b_r1 = *(const float4*)(Wp + k0 + 4);
        }
        #pragma unroll
        for (int kk = 0; kk < 8; kk++) {
            float4 a0 = *(const float4*)&As[cur][kk][tm*8];
            float4 a1 = *(const float4*)&As[cur][kk][tm*8+4];
            float4 b0 = *(const float4*)&Bs[cur][kk][tj*8];
            float4 b1v= *(const float4*)&Bs[cur][kk][tj*8+4];
            float av[8] = {a0.x,a0.y,a0.z,a0.w,a1.x,a1.y,a1.z,a1.w};
            float bv[8] = {b0.x,b0.y,b0.z,b0.w,b1v.x,b1v.y,b1v.z,b1v.w};
            #pragma unroll
            for (int i = 0; i < 8; i++)
                #pragma unroll
                for (int j = 0; j < 8; j++)
                    acc[i][j] = fmaf(av[i], bv[j], acc[i][j]);
        }
        if (nxt) {
            int nb = cur ^ 1;
            As[nb][ak+0][ar] = a_r.x; As[nb][ak+1][ar] = a_r.y;
            As[nb][ak+2][ar] = a_r.z; As[nb][ak+3][ar] = a_r.w;
            Bs[nb][0][tid] = b_r0.x; Bs[nb][1][tid] = b_r0.y;
            Bs[nb][2][tid] = b_r0.z; Bs[nb][3][tid] = b_r0.w;
            Bs[nb][4][tid] = b_r1.x; Bs[nb][5][tid] = b_r1.y;
            Bs[nb][6][tid] = b_r1.z; Bs[nb][7][tid] = b_r1.w;
        }
        __syncthreads();
    }

    int jc = j0 + tj * 8;
    float bb[8];
    #pragma unroll
    for (int j = 0; j < 8; j++)
        bb[j] = b1[jc+j] + (b2 ? b2[jc+j] : 0.0f);
    #pragma unroll
    for (int i = 0; i < 8; i++) {
        int row = row0 + tm * 8 + i;
        float4 v0 = make_float4(acc[i][0]+bb[0], acc[i][1]+bb[1],
                                acc[i][2]+bb[2], acc[i][3]+bb[3]);
        float4 v1 = make_float4(acc[i][4]+bb[4], acc[i][5]+bb[5],
                                acc[i][6]+bb[6], acc[i][7]+bb[7]);
        *(float4*)(C + (size_t)row * Hout + jc)     = v0;
        *(float4*)(C + (size_t)row * Hout + jc + 4) = v1;
    }
}

// ---- tensor-core helpers --------------------------------------------------------
__device__ __forceinline__ void mma_bf16(float* d, const unsigned* a, const unsigned* b) {
    asm volatile(
        "mma.sync.aligned.m16n8k16.row.col.f32.bf16.bf16.f32 "
        "{%0,%1,%2,%3}, {%4,%5,%6,%7}, {%8,%9}, {%0,%1,%2,%3};"
        : "+f"(d[0]), "+f"(d[1]), "+f"(d[2]), "+f"(d[3])
        : "r"(a[0]), "r"(a[1]), "r"(a[2]), "r"(a[3]), "r"(b[0]), "r"(b[1]));
}
__device__ __forceinline__ void ldsm_x4(unsigned* r, unsigned addr) {
    asm volatile("ldmatrix.sync.aligned.m8n8.x4.shared.b16 {%0,%1,%2,%3}, [%4];"
        : "=r"(r[0]), "=r"(r[1]), "=r"(r[2]), "=r"(r[3]) : "r"(addr));
}
__device__ __forceinline__ void ldsm_x2(unsigned* r, unsigned addr) {
    asm volatile("ldmatrix.sync.aligned.m8n8.x2.shared.b16 {%0,%1}, [%2];"
        : "=r"(r[0]), "=r"(r[1]) : "r"(addr));
}
// split pair (a,b) into packed bf16x2 hi and lo
__device__ __forceinline__ void split2(float a, float b, unsigned& hi, unsigned& lo) {
    __nv_bfloat162 h2 = __floats2bfloat162_rn(a, b);
    float ra = a - __bfloat162float(__low2bfloat16(h2));
    float rb = b - __bfloat162float(__high2bfloat16(h2));
    __nv_bfloat162 l2 = __floats2bfloat162_rn(ra, rb);
    hi = *(unsigned*)&h2; lo = *(unsigned*)&l2;
}

// smem byte offsets (dynamic). Rows are 128B (64 bf16); 16B units swizzled u^(row&7).
#define WS0HI  0
#define WS0LO  4096
#define WH1HI  8192
#define WH1LO  12288
#define WI1HI  16384
#define WI1LO  20480
#define HS0HI  24576
#define HS0LO  40960
#define HS1HI  57344
#define HS1LO  73728
#define B1S    90112
#define CSOFF  92160
#define SMEMB  94208

// ---- fused 2-layer wavefront recurrence, HMMA bf16-split phase 1 ----------------
// 128 CTAs = 16 j-tiles(32 cols) x 8 k-chunks(64). Protocol identical to R11.
__global__ __launch_bounds__(256)
void rnn6(const float* __restrict__ Whh0, const float* __restrict__ Whh1,
          const float* __restrict__ Wih1,
          const float* __restrict__ bih1, const float* __restrict__ bhh1)
{
    extern __shared__ char smc[];
    float* b1s = (float*)(smc + B1S);
    int*   cs  = (int*)(smc + CSOFF);
    __shared__ unsigned gen_sh;
    unsigned sb32 = (unsigned)__cvta_generic_to_shared(smc);

    int tid = threadIdx.x, cta = blockIdx.x;
    int jt = cta & 15, kc = cta >> 4;
    int j0 = jt * 32, k0 = kc * 64;

    // ---- one-time: zero hs arrays (stale-row safety), split weights, biases ----
    for (int i = tid; i < (16384 * 4) / 16; i += 256)
        ((uint4*)(smc + HS0HI))[i] = make_uint4(0, 0, 0, 0);
    {
        int j = tid >> 3, k8 = (tid & 7) * 8;          // j 0..31, k8 0..56
        int su = (k8 >> 3) ^ (j & 7);                  // swizzled 16B unit
        const float* srcs[3] = {
            Whh0 + (size_t)(j0 + j) * HH + k0 + k8,
            Whh1 + (size_t)(j0 + j) * HH + k0 + k8,
            Wih1 + (size_t)(j0 + j) * HH + k0 + k8 };
        int dsts[3] = {WS0HI, WH1HI, WI1HI};
        #pragma unroll
        for (int m = 0; m < 3; m++) {
            float4 x = *(const float4*)(srcs[m]);
            float4 y = *(const float4*)(srcs[m] + 4);
            unsigned h0w,h1w,h2w,h3w,l0w,l1w,l2w,l3w;
            split2(x.x, x.y, h0w, l0w); split2(x.z, x.w, h1w, l1w);
            split2(y.x, y.y, h2w, l2w); split2(y.z, y.w, h3w, l3w);
            *(uint4*)(smc + dsts[m] + j * 128 + su * 16) = make_uint4(h0w,h1w,h2w,h3w);
            *(uint4*)(smc + dsts[m] + 4096 + j * 128 + su * 16) = make_uint4(l0w,l1w,l2w,l3w);
        }
    }
    for (int i = tid; i < HH; i += 256) b1s[i] = bih1[i] + bhh1[i];
    for (int i = tid; i < TT; i += 256) cs[i] = g_cnt[i];
    if (tid == 0) gen_sh = g_bar_gen;
    __syncthreads();

    int n = tid >> 1, half = tid & 1;       // stage: 2 threads per row
    int w = tid >> 5, lane = tid & 31;
    // ldmatrix A lane addressing: rows w*16 + (lane&7) + 8*bit3, k-half = bit4
    int arow = w * 16 + (lane & 7) + ((lane >> 3) & 1) * 8;
    int asel = (lane >> 4) & 1;
    int abase = arow * 128;
    // ldmatrix B lane addressing (x2 uses lanes 0-15)
    int brow = lane & 7;
    int bsel = (lane >> 3) & 1;
    // output mapping
    int orow = w * 16 + (lane >> 2);
    int ocol = j0 + (lane & 3) * 2;

    for (int s = 0; s <= TT; s++) {
        int cnt0 = (s < TT) ? cs[s] : 0;
        int cnt1 = (s > 0) ? cs[s - 1] : 0;
        int sb = max(cnt0, cnt1);
        if (sb == 0) break;

        // ---- stage h -> bf16 hi/lo smem (swizzled), active rows only ----
        if (n < sb) {
            const float4* src = (const float4*)(g_h0 + (size_t)n * HH + k0 + half * 32);
            int swbase = n * 128;
            #pragma unroll
            for (int q = 0; q < 4; q++) {
                float4 x = __ldcg(src + q * 2);
                float4 y = __ldcg(src + q * 2 + 1);
                unsigned h0w,h1w,h2w,h3w,l0w,l1w,l2w,l3w;
                split2(x.x, x.y, h0w, l0w); split2(x.z, x.w, h1w, l1w);
                split2(y.x, y.y, h2w, l2w); split2(y.z, y.w, h3w, l3w);
                int su = (half * 4 + q) ^ (n & 7);
                *(uint4*)(smc + HS0HI + swbase + su * 16) = make_uint4(h0w,h1w,h2w,h3w);
                *(uint4*)(smc + HS0LO + swbase + su * 16) = make_uint4(l0w,l1w,l2w,l3w);
            }
        }
        if (n < cnt1) {
            const float4* src = (const float4*)(g_h1 + (size_t)n * HH + k0 + half * 32);
            int swbase = n * 128;
            #pragma unroll
            for (int q = 0; q < 4; q++) {
                float4 x = __ldcg(src + q * 2);
                float4 y = __ldcg(src + q * 2 + 1);
                unsigned h0w,h1w,h2w,h3w,l0w,l1w,l2w,l3w;
                split2(x.x, x.y, h0w, l0w); split2(x.z, x.w, h1w, l1w);
                split2(y.x, y.y, h2w, l2w); split2(y.z, y.w, h3w, l3w);
                int su = (half * 4 + q) ^ (n & 7);
                *(uint4*)(smc + HS1HI + swbase + su * 16) = make_uint4(h0w,h1w,h2w,h3w);
                *(uint4*)(smc + HS1LO + swbase + su * 16) = make_uint4(l0w,l1w,l2w,l3w);
            }
        }
        __syncthreads();

        // ---- phase 1: HMMA GEMMs ----
        bool act0 = (w * 16 < cnt0), act1 = (w * 16 < cnt1);
        if (act0 | act1) {
            float acc0[4][4] = {}, acc1[4][4] = {};
            #pragma unroll
            for (int kt = 0; kt < 4; kt++) {
                int au = ((kt * 2 + asel) ^ (arow & 7)) * 16;
                unsigned a0h[4], a0l[4], a1h[4], a1l[4];
                ldsm_x4(a0h, sb32 + HS0HI + abase + au);
                ldsm_x4(a0l, sb32 + HS0LO + abase + au);
                if (act1) {
                    ldsm_x4(a1h, sb32 + HS1HI + abase + au);
                    ldsm_x4(a1l, sb32 + HS1LO + abase + au);
                }
                #pragma unroll
                for (int nt = 0; nt < 4; nt++) {
                    int brr = nt * 8 + brow;
                    int boff = brr * 128 + ((kt * 2 + bsel) ^ (brr & 7)) * 16;
                    unsigned bh[2], bl[2];
                    if (act0) {
                        ldsm_x2(bh, sb32 + WS0HI + boff);
                        ldsm_x2(bl, sb32 + WS0LO + boff);
                        mma_bf16(acc0[nt], a0h, bh);
                        mma_bf16(acc0[nt], a0l, bh);
                        mma_bf16(acc0[nt], a0h, bl);
                    }
                    if (act1) {
                        ldsm_x2(bh, sb32 + WH1HI + boff);
                        ldsm_x2(bl, sb32 + WH1LO + boff);
                        mma_bf16(acc1[nt], a1h, bh);
                        mma_bf16(acc1[nt], a1l, bh);
                        mma_bf16(acc1[nt], a1h, bl);
                        ldsm_x2(bh, sb32 + WI1HI + boff);
                        ldsm_x2(bl, sb32 + WI1LO + boff);
                        mma_bf16(acc1[nt], a0h, bh);
                        mma_bf16(acc1[nt], a0l, bh);
                        mma_bf16(acc1[nt], a0h, bl);
                    }
                }
            }
            size_t pbase = (size_t)kc * NH;
            #pragma unroll
            for (int nt = 0; nt < 4; nt++) {
                int c = ocol + nt * 8;
                if (act0) {
                    *(float2*)&g_part0[pbase + (size_t)orow * HH + c] =
                        make_float2(acc0[nt][0], acc0[nt][1]);
                    *(float2*)&g_part0[pbase + (size_t)(orow + 8) * HH + c] =
                        make_float2(acc0[nt][2], acc0[nt][3]);
                }
                if (act1) {
                    *(float2*)&g_part1[pbase + (size_t)orow * HH + c] =
                        make_float2(acc1[nt][0], acc1[nt][1]);
                    *(float2*)&g_part1[pbase + (size_t)(orow + 8) * HH + c] =
                        make_float2(acc1[nt][2], acc1[nt][3]);
                }
            }
        }

        grid_barrier(&gen_sh, RNN_BLOCKS);

        // ---- phase 2: reduce + tanh + h updates (fp32, unchanged) ----
        if (cnt0 > 0) {
            const float* xpt = g_xp + (size_t)s * NH;
            int total = cnt0 * HH;
            for (int idx = cta * 256 + tid; idx < total; idx += RNN_BLOCKS * 256) {
                float v = xpt[idx];
                #pragma unroll
                for (int p = 0; p < 8; p++)
                    v += __ldcg(&g_part0[p * NH + idx]);
                g_h0[idx] = tanhf(v);
            }
        }
        if (cnt1 > 0) {
            int total = cnt1 * HH;
            for (int idx = cta * 256 + tid; idx < total; idx += RNN_BLOCKS * 256) {
                float v = b1s[idx & (HH - 1)];
                #pragma unroll
                for (int p = 0; p < 8; p++)
                    v += __ldcg(&g_part1[p * NH + idx]);
                g_h1[idx] = tanhf(v);
            }
        }

        grid_barrier(&gen_sh, RNN_BLOCKS);
    }
}

extern "C" void kernel_launch(void* const* d_in, const int* in_sizes, int n_in,
                              void* d_out, int out_size) {
    const float* x    = (const float*)d_in[0];
    const float* h0   = (const float*)d_in[1];
    const int*   len  = (const int*)  d_in[2];
    const float* Wih0 = (const float*)d_in[3];
    const float* bih0 = (const float*)d_in[4];
    const float* Whh0 = (const float*)d_in[5];
    const float* bhh0 = (const float*)d_in[6];
    const float* Wih1 = (const float*)d_in[7];
    const float* bih1 = (const float*)d_in[8];
    const float* Whh1 = (const float*)d_in[9];
    const float* bhh1 = (const float*)d_in[10];
    const float* Wfc  = (const float*)d_in[11];
    const float* bfc  = (const float*)d_in[12];
    float* out = (float*)d_out;

    static int smem_set = 0;
    if (!smem_set) {
        cudaFuncSetAttribute(rnn6, cudaFuncAttributeMaxDynamicSharedMemorySize, SMEMB);
        smem_set = 1;
    }

    count_kernel<<<1, TT>>>(len);
    init_h_kernel<<<NH/256, 256>>>(h0);

    // layer-0 xproj (+ both layer-0 biases)
    gemm64<<<dim3(HH/128, TT*2), 128>>>(x, 0, Wih0, bih0, bhh0, nullptr, 0, II, HH, 1);

    // fused 2-layer wavefront recurrence (tensor-core phase 1)
    rnn6<<<RNN_BLOCKS, 256, SMEMB>>>(Whh0, Whh1, Wih1, bih1, bhh1);

    copy_h_kernel<<<NH/256, 256>>>(out);

    // logits = h1_final @ Wfc^T + bfc
    gemm64<<<dim3(CC/128, NN/64), 128>>>(nullptr, 1, Wfc, bfc, nullptr, out, 1, HH, CC, 0);
}

// round 14
// speedup vs baseline: 2.9337x; 1.2271x over previous
#include <cuda_runtime.h>
#include <cuda_bf16.h>
#include <math.h>

#define TT 512
#define NN 128
#define II 256
#define HH 512
#define CC 128
#define NH (NN*HH)
#define RNN_BLOCKS 128
#define H_OFF (NN*CC)

__device__ float g_xp[TT*NN*HH];      // layer-0 xproj (+both layer-0 biases)
__device__ __align__(16) __nv_bfloat16 g_hb0hi[NH];   // h, pre-split bf16
__device__ __align__(16) __nv_bfloat16 g_hb0lo[NH];
__device__ __align__(16) __nv_bfloat16 g_hb1hi[NH];
__device__ __align__(16) __nv_bfloat16 g_hb1lo[NH];
__device__ float g_hf[NH];            // reconstructed h1 (logits input)
__device__ float g_part0[8*NH];       // k-split partials, layer 0
__device__ float g_part1[8*NH];       // k-split partials, layer 1
__device__ int   g_cnt[TT];
__device__ unsigned g_bar_count;
__device__ volatile unsigned g_bar_gen;

// ---- grid barrier: PROVEN flat idiom (R2/R4/R10/R11/R12). DO NOT CHANGE. -------
__device__ __forceinline__ void grid_barrier(unsigned* gen_sh, int nblk) {
    __syncthreads();
    if (threadIdx.x == 0) {
        unsigned g = *gen_sh;
        __threadfence();
        unsigned prev = atomicAdd(&g_bar_count, 1u);
        if (prev == (unsigned)(nblk - 1)) {
            g_bar_count = 0u;
            __threadfence();
            g_bar_gen = g + 1u;
        } else {
            while (g_bar_gen == g) { }
        }
        *gen_sh = g + 1u;
    }
    __syncthreads();
}

__global__ void count_kernel(const int* __restrict__ len) {
    int t = threadIdx.x, c = 0;
    #pragma unroll 8
    for (int n = 0; n < NN; n++) c += (len[n] > t) ? 1 : 0;
    g_cnt[t] = c;
}

__global__ void init_h_kernel(const float* __restrict__ h0) {
    int i = blockIdx.x * blockDim.x + threadIdx.x;
    if (i < NH) {
        float a = h0[i];
        __nv_bfloat16 ah = __float2bfloat16(a);
        g_hb0hi[i] = ah;
        g_hb0lo[i] = __float2bfloat16(a - __bfloat162float(ah));
        float b = h0[NH + i];
        __nv_bfloat16 bh = __float2bfloat16(b);
        g_hb1hi[i] = bh;
        g_hb1lo[i] = __float2bfloat16(b - __bfloat162float(bh));
    }
}

__global__ void copy_h_kernel(float* __restrict__ dout) {
    int i = blockIdx.x * blockDim.x + threadIdx.x;
    if (i < NH) {
        float v0 = __bfloat162float(g_hb0hi[i]) + __bfloat162float(g_hb0lo[i]);
        float v1 = __bfloat162float(g_hb1hi[i]) + __bfloat162float(g_hb1lo[i]);
        dout[H_OFF + i]      = v0;
        dout[H_OFF + NH + i] = v1;
        g_hf[i] = v1;
    }
}

// ---- input GEMM + bias (unchanged, proven): 64x128 tile fp32 -------------------
__global__ __launch_bounds__(128)
void gemm64(const float* __restrict__ Aptr, int asel,
            const float* __restrict__ W,
            const float* __restrict__ b1, const float* __restrict__ b2,
            float* __restrict__ Cptr, int csel, int K, int Hout, int useCnt)
{
    const float* A = (asel == 0) ? Aptr : g_hf;
    float* C = (csel == 0) ? g_xp : Cptr;

    int row0;
    if (useCnt) {
        int t = blockIdx.y >> 1, nt = blockIdx.y & 1;
        if (nt * 64 >= g_cnt[t]) return;
        row0 = t * NN + nt * 64;
    } else {
        row0 = blockIdx.y * 64;
    }
    int j0 = blockIdx.x * 128;
    int tid = threadIdx.x;

    __shared__ float As[2][8][68];
    __shared__ float Bs[2][8][132];

    int ar = tid >> 1;
    int ak = (tid & 1) * 4;
    const float* Ap = A + (size_t)(row0 + ar) * K + ak;
    const float* Wp = W + (size_t)(j0 + tid) * K;
    int KT = K >> 3;

    float4 a_r  = *(const float4*)(Ap);
    float4 b_r0 = *(const float4*)(Wp);
    float4 b_r1 = *(const float4*)(Wp + 4);
    As[0][ak+0][ar] = a_r.x; As[0][ak+1][ar] = a_r.y;
    As[0][ak+2][ar] = a_r.z; As[0][ak+3][ar] = a_r.w;
    Bs[0][0][tid] = b_r0.x; Bs[0][1][tid] = b_r0.y;
    Bs[0][2][tid] = b_r0.z; Bs[0][3][tid] = b_r0.w;
    Bs[0][4][tid] = b_r1.x; Bs[0][5][tid] = b_r1.y;
    Bs[0][6][tid] = b_r1.z; Bs[0][7][tid] = b_r1.w;
    __syncthreads();

    int tm = tid & 7;
    int tj = tid >> 3;
    float acc[8][8] = {};

    for (int kt = 0; kt < KT; kt++) {
        int cur = kt & 1;
        bool nxt = (kt + 1 < KT);
        if (nxt) {
            int k0 = (kt + 1) << 3;
            a_r  = *(const float4*)(Ap + k0);
            b_r0 = *(const float4*)(Wp + k0);
            b_r1 = *(const float4*)(Wp + k0 + 4);
        }
        #pragma unroll
        for (int kk = 0; kk < 8; kk++) {
            float4 a0 = *(const float4*)&As[cur][kk][tm*8];
            float4 a1 = *(const float4*)&As[cur][kk][tm*8+4];
            float4 b0 = *(const float4*)&Bs[cur][kk][tj*8];
            float4 b1v= *(const float4*)&Bs[cur][kk][tj*8+4];
            float av[8] = {a0.x,a0.y,a0.z,a0.w,a1.x,a1.y,a1.z,a1.w};
            float bv[8] = {b0.x,b0.y,b0.z,b0.w,b1v.x,b1v.y,b1v.z,b1v.w};
            #pragma unroll
            for (int i = 0; i < 8; i++)
                #pragma unroll
                for (int j = 0; j < 8; j++)
                    acc[i][j] = fmaf(av[i], bv[j], acc[i][j]);
        }
        if (nxt) {
            int nb = cur ^ 1;
            As[nb][ak+0][ar] = a_r.x; As[nb][ak+1][ar] = a_r.y;
            As[nb][ak+2][ar] = a_r.z; As[nb][ak+3][ar] = a_r.w;
            Bs[nb][0][tid] = b_r0.x; Bs[nb][1][tid] = b_r0.y;
            Bs[nb][2][tid] = b_r0.z; Bs[nb][3][tid] = b_r0.w;
            Bs[nb][4][tid] = b_r1.x; Bs[nb][5][tid] = b_r1.y;
            Bs[nb][6][tid] = b_r1.z; Bs[nb][7][tid] = b_r1.w;
        }
        __syncthreads();
    }

    int jc = j0 + tj * 8;
    float bb[8];
    #pragma unroll
    for (int j = 0; j < 8; j++)
        bb[j] = b1[jc+j] + (b2 ? b2[jc+j] : 0.0f);
    #pragma unroll
    for (int i = 0; i < 8; i++) {
        int row = row0 + tm * 8 + i;
        float4 v0 = make_float4(acc[i][0]+bb[0], acc[i][1]+bb[1],
                                acc[i][2]+bb[2], acc[i][3]+bb[3]);
        float4 v1 = make_float4(acc[i][4]+bb[4], acc[i][5]+bb[5],
                                acc[i][6]+bb[6], acc[i][7]+bb[7]);
        *(float4*)(C + (size_t)row * Hout + jc)     = v0;
        *(float4*)(C + (size_t)row * Hout + jc + 4) = v1;
    }
}

// ---- tensor-core helpers --------------------------------------------------------
__device__ __forceinline__ void mma_bf16(float* d, const unsigned* a, const unsigned* b) {
    asm volatile(
        "mma.sync.aligned.m16n8k16.row.col.f32.bf16.bf16.f32 "
        "{%0,%1,%2,%3}, {%4,%5,%6,%7}, {%8,%9}, {%0,%1,%2,%3};"
        : "+f"(d[0]), "+f"(d[1]), "+f"(d[2]), "+f"(d[3])
        : "r"(a[0]), "r"(a[1]), "r"(a[2]), "r"(a[3]), "r"(b[0]), "r"(b[1]));
}
__device__ __forceinline__ void ldsm_x4(unsigned* r, unsigned addr) {
    asm volatile("ldmatrix.sync.aligned.m8n8.x4.shared.b16 {%0,%1,%2,%3}, [%4];"
        : "=r"(r[0]), "=r"(r[1]), "=r"(r[2]), "=r"(r[3]) : "r"(addr));
}
// split pair (a,b) into packed bf16x2 hi and lo
__device__ __forceinline__ void split2(float a, float b, unsigned& hi, unsigned& lo) {
    __nv_bfloat162 h2 = __floats2bfloat162_rn(a, b);
    float ra = a - __bfloat162float(__low2bfloat16(h2));
    float rb = b - __bfloat162float(__high2bfloat16(h2));
    __nv_bfloat162 l2 = __floats2bfloat162_rn(ra, rb);
    hi = *(unsigned*)&h2; lo = *(unsigned*)&l2;
}

// smem byte offsets (dynamic). Rows are 128B (64 bf16); 16B units swizzled u^(row&7).
#define WS0HI  0
#define WS0LO  4096
#define WH1HI  8192
#define WH1LO  12288
#define WI1HI  16384
#define WI1LO  20480
#define HS0HI  24576
#define HS0LO  40960
#define HS1HI  57344
#define HS1LO  73728
#define B1S    90112
#define CSOFF  92160
#define SMEMB  94208

// ---- fused 2-layer wavefront recurrence, HMMA bf16-split phase 1 ----------------
// 128 CTAs = 16 j-tiles(32 cols) x 8 k-chunks(64). Protocol identical to R12.
__global__ __launch_bounds__(256)
void rnn6(const float* __restrict__ Whh0, const float* __restrict__ Whh1,
          const float* __restrict__ Wih1,
          const float* __restrict__ bih1, const float* __restrict__ bhh1)
{
    extern __shared__ char smc[];
    float* b1s = (float*)(smc + B1S);
    int*   cs  = (int*)(smc + CSOFF);
    __shared__ unsigned gen_sh;
    unsigned sb32 = (unsigned)__cvta_generic_to_shared(smc);

    int tid = threadIdx.x, cta = blockIdx.x;
    int jt = cta & 15, kc = cta >> 4;
    int j0 = jt * 32, k0 = kc * 64;

    // ---- one-time: zero hs arrays (stale-row safety), split weights, biases ----
    for (int i = tid; i < (16384 * 4) / 16; i += 256)
        ((uint4*)(smc + HS0HI))[i] = make_uint4(0, 0, 0, 0);
    {
        int j = tid >> 3, k8 = (tid & 7) * 8;          // j 0..31, k8 0..56
        int su = (k8 >> 3) ^ (j & 7);                  // swizzled 16B unit
        const float* srcs[3] = {
            Whh0 + (size_t)(j0 + j) * HH + k0 + k8,
            Whh1 + (size_t)(j0 + j) * HH + k0 + k8,
            Wih1 + (size_t)(j0 + j) * HH + k0 + k8 };
        int dsts[3] = {WS0HI, WH1HI, WI1HI};
        #pragma unroll
        for (int m = 0; m < 3; m++) {
            float4 x = *(const float4*)(srcs[m]);
            float4 y = *(const float4*)(srcs[m] + 4);
            unsigned h0w,h1w,h2w,h3w,l0w,l1w,l2w,l3w;
            split2(x.x, x.y, h0w, l0w); split2(x.z, x.w, h1w, l1w);
            split2(y.x, y.y, h2w, l2w); split2(y.z, y.w, h3w, l3w);
            *(uint4*)(smc + dsts[m] + j * 128 + su * 16) = make_uint4(h0w,h1w,h2w,h3w);
            *(uint4*)(smc + dsts[m] + 4096 + j * 128 + su * 16) = make_uint4(l0w,l1w,l2w,l3w);
        }
    }
    for (int i = tid; i < HH; i += 256) b1s[i] = bih1[i] + bhh1[i];
    for (int i = tid; i < TT; i += 256) cs[i] = g_cnt[i];
    if (tid == 0) gen_sh = g_bar_gen;
    __syncthreads();

    int n = tid >> 1, half = tid & 1;       // stage: 2 threads per row
    int w = tid >> 5, lane = tid & 31;
    int arow = w * 16 + (lane & 7) + ((lane >> 3) & 1) * 8;
    int asel = (lane >> 4) & 1;
    int abase = arow * 128;
    int bgrp = ((lane >> 4) & 1) * 8 + (lane & 7);   // nt-within-pair * 8 + row
    int bsel = (lane >> 3) & 1;
    int orow = w * 16 + (lane >> 2);
    int ocol = j0 + (lane & 3) * 2;

    for (int s = 0; s <= TT; s++) {
        int cnt0 = (s < TT) ? cs[s] : 0;
        int cnt1 = (s > 0) ? cs[s - 1] : 0;
        int sb = max(cnt0, cnt1);
        if (sb == 0) break;

        // ---- stage pre-split h -> smem (pure 16B copies, swizzled) ----
        if (n < sb) {
            size_t eoff = (size_t)n * HH + k0 + half * 32;
            const uint4* shi = (const uint4*)(g_hb0hi + eoff);
            const uint4* slo = (const uint4*)(g_hb0lo + eoff);
            int swbase = n * 128;
            #pragma unroll
            for (int q = 0; q < 4; q++) {
                int su = (half * 4 + q) ^ (n & 7);
                *(uint4*)(smc + HS0HI + swbase + su * 16) = __ldcg(shi + q);
                *(uint4*)(smc + HS0LO + swbase + su * 16) = __ldcg(slo + q);
            }
        }
        if (n < cnt1) {
            size_t eoff = (size_t)n * HH + k0 + half * 32;
            const uint4* shi = (const uint4*)(g_hb1hi + eoff);
            const uint4* slo = (const uint4*)(g_hb1lo + eoff);
            int swbase = n * 128;
            #pragma unroll
            for (int q = 0; q < 4; q++) {
                int su = (half * 4 + q) ^ (n & 7);
                *(uint4*)(smc + HS1HI + swbase + su * 16) = __ldcg(shi + q);
                *(uint4*)(smc + HS1LO + swbase + su * 16) = __ldcg(slo + q);
            }
        }
        __syncthreads();

        // ---- phase 1: HMMA GEMMs (x4 B-fragment loads) ----
        bool act0 = (w * 16 < cnt0), act1 = (w * 16 < cnt1);
        if (act0 | act1) {
            float acc0[4][4] = {}, acc1[4][4] = {};
            #pragma unroll
            for (int kt = 0; kt < 4; kt++) {
                int au = ((kt * 2 + asel) ^ (arow & 7)) * 16;
                unsigned a0h[4], a0l[4], a1h[4], a1l[4];
                ldsm_x4(a0h, sb32 + HS0HI + abase + au);
                ldsm_x4(a0l, sb32 + HS0LO + abase + au);
                if (act1) {
                    ldsm_x4(a1h, sb32 + HS1HI + abase + au);
                    ldsm_x4(a1l, sb32 + HS1LO + abase + au);
                }
                #pragma unroll
                for (int ntp = 0; ntp < 2; ntp++) {
                    int brr = ntp * 16 + bgrp;
                    int boff = brr * 128 + (((kt * 2 + bsel) ^ (brr & 7)) * 16);
                    unsigned b4[4];
                    if (act0) {
                        ldsm_x4(b4, sb32 + WS0HI + boff);
                        mma_bf16(acc0[ntp*2],   a0h, b4);
                        mma_bf16(acc0[ntp*2+1], a0h, b4 + 2);
                        mma_bf16(acc0[ntp*2],   a0l, b4);
                        mma_bf16(acc0[ntp*2+1], a0l, b4 + 2);
                        ldsm_x4(b4, sb32 + WS0LO + boff);
                        mma_bf16(acc0[ntp*2],   a0h, b4);
                        mma_bf16(acc0[ntp*2+1], a0h, b4 + 2);
                    }
                    if (act1) {
                        ldsm_x4(b4, sb32 + WH1HI + boff);
                        mma_bf16(acc1[ntp*2],   a1h, b4);
                        mma_bf16(acc1[ntp*2+1], a1h, b4 + 2);
                        mma_bf16(acc1[ntp*2],   a1l, b4);
                        mma_bf16(acc1[ntp*2+1], a1l, b4 + 2);
                        ldsm_x4(b4, sb32 + WH1LO + boff);
                        mma_bf16(acc1[ntp*2],   a1h, b4);
                        mma_bf16(acc1[ntp*2+1], a1h, b4 + 2);
                        ldsm_x4(b4, sb32 + WI1HI + boff);
                        mma_bf16(acc1[ntp*2],   a0h, b4);
                        mma_bf16(acc1[ntp*2+1], a0h, b4 + 2);
                        mma_bf16(acc1[ntp*2],   a0l, b4);
                        mma_bf16(acc1[ntp*2+1], a0l, b4 + 2);
                        ldsm_x4(b4, sb32 + WI1LO + boff);
                        mma_bf16(acc1[ntp*2],   a0h, b4);
                        mma_bf16(acc1[ntp*2+1], a0h, b4 + 2);
                    }
                }
            }
            size_t pbase = (size_t)kc * NH;
            #pragma unroll
            for (int nt = 0; nt < 4; nt++) {
                int c = ocol + nt * 8;
                if (act0) {
                    *(float2*)&g_part0[pbase + (size_t)orow * HH + c] =
                        make_float2(acc0[nt][0], acc0[nt][1]);
                    *(float2*)&g_part0[pbase + (size_t)(orow + 8) * HH + c] =
                        make_float2(acc0[nt][2], acc0[nt][3]);
                }
                if (act1) {
                    *(float2*)&g_part1[pbase + (size_t)orow * HH + c] =
                        make_float2(acc1[nt][0], acc1[nt][1]);
                    *(float2*)&g_part1[pbase + (size_t)(orow + 8) * HH + c] =
                        make_float2(acc1[nt][2], acc1[nt][3]);
                }
            }
        }

        grid_barrier(&gen_sh, RNN_BLOCKS);

        // ---- phase 2: vectorized reduce + tanh + split-store h ----
        if (cnt0 > 0) {
            const float4* xp4 = (const float4*)(g_xp + (size_t)s * NH);
            int total4 = cnt0 * (HH / 4);
            for (int v = cta * 256 + tid; v < total4; v += RNN_BLOCKS * 256) {
                float4 sum = xp4[v];
                #pragma unroll
                for (int p = 0; p < 8; p++) {
                    float4 pp = __ldcg((const float4*)g_part0 + (size_t)p * (NH/4) + v);
                    sum.x += pp.x; sum.y += pp.y; sum.z += pp.z; sum.w += pp.w;
                }
                float t0 = tanhf(sum.x), t1 = tanhf(sum.y);
                float t2 = tanhf(sum.z), t3 = tanhf(sum.w);
                unsigned h01, l01, h23, l23;
                split2(t0, t1, h01, l01); split2(t2, t3, h23, l23);
                ((uint2*)g_hb0hi)[v] = make_uint2(h01, h23);
                ((uint2*)g_hb0lo)[v] = make_uint2(l01, l23);
            }
        }
        if (cnt1 > 0) {
            int total4 = cnt1 * (HH / 4);
            for (int v = cta * 256 + tid; v < total4; v += RNN_BLOCKS * 256) {
                float4 sum = *(const float4*)&b1s[(v * 4) & (HH - 1)];
                #pragma unroll
                for (int p = 0; p < 8; p++) {
                    float4 pp = __ldcg((const float4*)g_part1 + (size_t)p * (NH/4) + v);
                    sum.x += pp.x; sum.y += pp.y; sum.z += pp.z; sum.w += pp.w;
                }
                float t0 = tanhf(sum.x), t1 = tanhf(sum.y);
                float t2 = tanhf(sum.z), t3 = tanhf(sum.w);
                unsigned h01, l01, h23, l23;
                split2(t0, t1, h01, l01); split2(t2, t3, h23, l23);
                ((uint2*)g_hb1hi)[v] = make_uint2(h01, h23);
                ((uint2*)g_hb1lo)[v] = make_uint2(l01, l23);
            }
        }

        grid_barrier(&gen_sh, RNN_BLOCKS);
    }
}

extern "C" void kernel_launch(void* const* d_in, const int* in_sizes, int n_in,
                              void* d_out, int out_size) {
    const float* x    = (const float*)d_in[0];
    const float* h0   = (const float*)d_in[1];
    const int*   len  = (const int*)  d_in[2];
    const float* Wih0 = (const float*)d_in[3];
    const float* bih0 = (const float*)d_in[4];
    const float* Whh0 = (const float*)d_in[5];
    const float* bhh0 = (const float*)d_in[6];
    const float* Wih1 = (const float*)d_in[7];
    const float* bih1 = (const float*)d_in[8];
    const float* Whh1 = (const float*)d_in[9];
    const float* bhh1 = (const float*)d_in[10];
    const float* Wfc  = (const float*)d_in[11];
    const float* bfc  = (const float*)d_in[12];
    float* out = (float*)d_out;

    static int smem_set = 0;
    if (!smem_set) {
        cudaFuncSetAttribute(rnn6, cudaFuncAttributeMaxDynamicSharedMemorySize, SMEMB);
        smem_set = 1;
    }

    count_kernel<<<1, TT>>>(len);
    init_h_kernel<<<NH/256, 256>>>(h0);

    // layer-0 xproj (+ both layer-0 biases)
    gemm64<<<dim3(HH/128, TT*2), 128>>>(x, 0, Wih0, bih0, bhh0, nullptr, 0, II, HH, 1);

    // fused 2-layer wavefront recurrence (tensor-core phase 1)
    rnn6<<<RNN_BLOCKS, 256, SMEMB>>>(Whh0, Whh1, Wih1, bih1, bhh1);

    copy_h_kernel<<<NH/256, 256>>>(out);

    // logits = h1_final @ Wfc^T + bfc
    gemm64<<<dim3(CC/128, NN/64), 128>>>(nullptr, 1, Wfc, bfc, nullptr, out, 1, HH, CC, 0);
}

// round 15
// speedup vs baseline: 2.9997x; 1.0225x over previous
#include <cuda_runtime.h>
#include <cuda_bf16.h>
#include <math.h>

#define TT 512
#define NN 128
#define II 256
#define HH 512
#define CC 128
#define NH (NN*HH)
#define RNN_BLOCKS 128
#define H_OFF (NN*CC)

__device__ float g_xp[TT*NN*HH];      // layer-0 xproj (+both layer-0 biases)
__device__ __align__(16) __nv_bfloat16 g_hb0hi[NH];   // h, pre-split bf16
__device__ __align__(16) __nv_bfloat16 g_hb0lo[NH];
__device__ __align__(16) __nv_bfloat16 g_hb1hi[NH];
__device__ __align__(16) __nv_bfloat16 g_hb1lo[NH];
__device__ float g_hf[NH];            // reconstructed h1 (logits input)
__device__ float g_part0[8*NH];       // k-split partials, layer 0
__device__ float g_part1[8*NH];       // k-split partials, layer 1
__device__ int   g_cnt[TT];
__device__ unsigned g_bar_count;
__device__ volatile unsigned g_bar_gen;

// ---- grid barrier: PROVEN flat idiom (R2/R4/R10/R11/R12/R14). DO NOT CHANGE. ---
__device__ __forceinline__ void grid_barrier(unsigned* gen_sh, int nblk) {
    __syncthreads();
    if (threadIdx.x == 0) {
        unsigned g = *gen_sh;
        __threadfence();
        unsigned prev = atomicAdd(&g_bar_count, 1u);
        if (prev == (unsigned)(nblk - 1)) {
            g_bar_count = 0u;
            __threadfence();
            g_bar_gen = g + 1u;
        } else {
            while (g_bar_gen == g) { }
        }
        *gen_sh = g + 1u;
    }
    __syncthreads();
}

__global__ void count_kernel(const int* __restrict__ len) {
    int t = threadIdx.x, c = 0;
    #pragma unroll 8
    for (int n = 0; n < NN; n++) c += (len[n] > t) ? 1 : 0;
    g_cnt[t] = c;
}

__global__ void init_h_kernel(const float* __restrict__ h0) {
    int i = blockIdx.x * blockDim.x + threadIdx.x;
    if (i < NH) {
        float a = h0[i];
        __nv_bfloat16 ah = __float2bfloat16(a);
        g_hb0hi[i] = ah;
        g_hb0lo[i] = __float2bfloat16(a - __bfloat162float(ah));
        float b = h0[NH + i];
        __nv_bfloat16 bh = __float2bfloat16(b);
        g_hb1hi[i] = bh;
        g_hb1lo[i] = __float2bfloat16(b - __bfloat162float(bh));
    }
}

__global__ void copy_h_kernel(float* __restrict__ dout) {
    int i = blockIdx.x * blockDim.x + threadIdx.x;
    if (i < NH) {
        float v0 = __bfloat162float(g_hb0hi[i]) + __bfloat162float(g_hb0lo[i]);
        float v1 = __bfloat162float(g_hb1hi[i]) + __bfloat162float(g_hb1lo[i]);
        dout[H_OFF + i]      = v0;
        dout[H_OFF + NH + i] = v1;
        g_hf[i] = v1;
    }
}

// ---- tensor-core helpers --------------------------------------------------------
__device__ __forceinline__ void mma_bf16(float* d, const unsigned* a, const unsigned* b) {
    asm volatile(
        "mma.sync.aligned.m16n8k16.row.col.f32.bf16.bf16.f32 "
        "{%0,%1,%2,%3}, {%4,%5,%6,%7}, {%8,%9}, {%0,%1,%2,%3};"
        : "+f"(d[0]), "+f"(d[1]), "+f"(d[2]), "+f"(d[3])
        : "r"(a[0]), "r"(a[1]), "r"(a[2]), "r"(a[3]), "r"(b[0]), "r"(b[1]));
}
__device__ __forceinline__ void ldsm_x4(unsigned* r, unsigned addr) {
    asm volatile("ldmatrix.sync.aligned.m8n8.x4.shared.b16 {%0,%1,%2,%3}, [%4];"
        : "=r"(r[0]), "=r"(r[1]), "=r"(r[2]), "=r"(r[3]) : "r"(addr));
}
// split pair (a,b) into packed bf16x2 hi and lo
__device__ __forceinline__ void split2(float a, float b, unsigned& hi, unsigned& lo) {
    __nv_bfloat162 h2 = __floats2bfloat162_rn(a, b);
    float ra = a - __bfloat162float(__low2bfloat16(h2));
    float rb = b - __bfloat162float(__high2bfloat16(h2));
    __nv_bfloat162 l2 = __floats2bfloat162_rn(ra, rb);
    hi = *(unsigned*)&h2; lo = *(unsigned*)&l2;
}

// ---- xp0 GEMM on tensor cores: xp[t,n,j] = x[t,n,:] . Wih0[j,:] + bih0 + bhh0 ---
// grid (4 j-tiles of 128, TT). 256 thr. K=256 in 4 chunks of 64. Fragment/swizzle
// patterns identical to the silicon-proven rnn6 path.
#define XHI 0
#define XLO 16384
#define WHI 32768
#define WLO 49152
#define XBS 65536
#define XSMEM 66048
__global__ __launch_bounds__(256)
void xp_hmma(const float* __restrict__ x, const float* __restrict__ Wih0,
             const float* __restrict__ bih0, const float* __restrict__ bhh0)
{
    int t = blockIdx.y;
    int cnt = g_cnt[t];
    if (cnt == 0) return;
    int jt = blockIdx.x;
    extern __shared__ char smc[];
    float* bsum = (float*)(smc + XBS);
    unsigned sb32 = (unsigned)__cvta_generic_to_shared(smc);

    int tid = threadIdx.x;
    int w = tid >> 5, lane = tid & 31;
    int arow = w * 16 + (lane & 7) + ((lane >> 3) & 1) * 8;
    int asel = (lane >> 4) & 1;
    int abase = arow * 128;
    int bgrp = ((lane >> 4) & 1) * 8 + (lane & 7);
    int bsel = (lane >> 3) & 1;

    if (tid < 128) bsum[tid] = bih0[jt * 128 + tid] + bhh0[jt * 128 + tid];

    bool actw = (w * 16 < cnt);
    float acc[16][4] = {};

    int r = tid >> 1, half = tid & 1;
    #pragma unroll 1
    for (int kc = 0; kc < 4; kc++) {
        __syncthreads();
        {   // stage x chunk and W chunk (split to hi/lo bf16, swizzled)
            const float4* xs = (const float4*)(x + ((size_t)t * NN + r) * II + kc * 64 + half * 32);
            const float4* ws = (const float4*)(Wih0 + (size_t)(jt * 128 + r) * II + kc * 64 + half * 32);
            int swbase = r * 128;
            #pragma unroll
            for (int q = 0; q < 4; q++) {
                int su = (half * 4 + q) ^ (r & 7);
                float4 a = xs[q * 2], b = xs[q * 2 + 1];
                unsigned h0w,h1w,h2w,h3w,l0w,l1w,l2w,l3w;
                split2(a.x, a.y, h0w, l0w); split2(a.z, a.w, h1w, l1w);
                split2(b.x, b.y, h2w, l2w); split2(b.z, b.w, h3w, l3w);
                *(uint4*)(smc + XHI + swbase + su * 16) = make_uint4(h0w,h1w,h2w,h3w);
                *(uint4*)(smc + XLO + swbase + su * 16) = make_uint4(l0w,l1w,l2w,l3w);
                a = ws[q * 2]; b = ws[q * 2 + 1];
                split2(a.x, a.y, h0w, l0w); split2(a.z, a.w, h1w, l1w);
                split2(b.x, b.y, h2w, l2w); split2(b.z, b.w, h3w, l3w);
                *(uint4*)(smc + WHI + swbase + su * 16) = make_uint4(h0w,h1w,h2w,h3w);
                *(uint4*)(smc + WLO + swbase + su * 16) = make_uint4(l0w,l1w,l2w,l3w);
            }
        }
        __syncthreads();

        if (actw) {
            #pragma unroll
            for (int kt = 0; kt < 4; kt++) {
                int au = ((kt * 2 + asel) ^ (arow & 7)) * 16;
                unsigned ah[4], al[4];
                ldsm_x4(ah, sb32 + XHI + abase + au);
                ldsm_x4(al, sb32 + XLO + abase + au);
                #pragma unroll
                for (int ntp = 0; ntp < 8; ntp++) {
                    int brr = ntp * 16 + bgrp;
                    int boff = brr * 128 + (((kt * 2 + bsel) ^ (brr & 7)) * 16);
                    unsigned b4[4];
                    ldsm_x4(b4, sb32 + WHI + boff);
                    mma_bf16(acc[ntp*2],   ah, b4);
                    mma_bf16(acc[ntp*2+1], ah, b4 + 2);
                    mma_bf16(acc[ntp*2],   al, b4);
                    mma_bf16(acc[ntp*2+1], al, b4 + 2);
                    ldsm_x4(b4, sb32 + WLO + boff);
                    mma_bf16(acc[ntp*2],   ah, b4);
                    mma_bf16(acc[ntp*2+1], ah, b4 + 2);
                }
            }
        }
    }

    if (actw) {
        int lr = lane >> 2, lc = (lane & 3) * 2;
        int r0 = w * 16 + lr;
        #pragma unroll
        for (int nt = 0; nt < 16; nt++) {
            int cl = nt * 8 + lc;
            float b0 = bsum[cl], b1 = bsum[cl + 1];
            if (r0 < cnt)
                *(float2*)&g_xp[((size_t)t * NN + r0) * HH + jt * 128 + cl] =
                    make_float2(acc[nt][0] + b0, acc[nt][1] + b1);
            if (r0 + 8 < cnt)
                *(float2*)&g_xp[((size_t)t * NN + r0 + 8) * HH + jt * 128 + cl] =
                    make_float2(acc[nt][2] + b0, acc[nt][3] + b1);
        }
    }
}

// ---- logits GEMM (fp32, small): C[m,j] = g_hf[m,:512] . Wfc[j,:] + bfc ---------
__global__ __launch_bounds__(128)
void gemm64(const float* __restrict__ W, const float* __restrict__ b1,
            float* __restrict__ C, int K, int Hout)
{
    int row0 = blockIdx.y * 64;
    int j0 = blockIdx.x * 128;
    int tid = threadIdx.x;

    __shared__ float As[2][8][68];
    __shared__ float Bs[2][8][132];

    int ar = tid >> 1;
    int ak = (tid & 1) * 4;
    const float* Ap = g_hf + (size_t)(row0 + ar) * K + ak;
    const float* Wp = W + (size_t)(j0 + tid) * K;
    int KT = K >> 3;

    float4 a_r  = *(const float4*)(Ap);
    float4 b_r0 = *(const float4*)(Wp);
    float4 b_r1 = *(const float4*)(Wp + 4);
    As[0][ak+0][ar] = a_r.x; As[0][ak+1][ar] = a_r.y;
    As[0][ak+2][ar] = a_r.z; As[0][ak+3][ar] = a_r.w;
    Bs[0][0][tid] = b_r0.x; Bs[0][1][tid] = b_r0.y;
    Bs[0][2][tid] = b_r0.z; Bs[0][3][tid] = b_r0.w;
    Bs[0][4][tid] = b_r1.x; Bs[0][5][tid] = b_r1.y;
    Bs[0][6][tid] = b_r1.z; Bs[0][7][tid] = b_r1.w;
    __syncthreads();

    int tm = tid & 7;
    int tj = tid >> 3;
    float acc[8][8] = {};

    for (int kt = 0; kt < KT; kt++) {
        int cur = kt & 1;
        bool nxt = (kt + 1 < KT);
        if (nxt) {
            int k0 = (kt + 1) << 3;
            a_r  = *(const float4*)(Ap + k0);
            b_r0 = *(const float4*)(Wp + k0);
            b_r1 = *(const float4*)(Wp + k0 + 4);
        }
        #pragma unroll
        for (int kk = 0; kk < 8; kk++) {
            float4 a0 = *(const float4*)&As[cur][kk][tm*8];
            float4 a1 = *(const float4*)&As[cur][kk][tm*8+4];
            float4 b0 = *(const float4*)&Bs[cur][kk][tj*8];
            float4 b1v= *(const float4*)&Bs[cur][kk][tj*8+4];
            float av[8] = {a0.x,a0.y,a0.z,a0.w,a1.x,a1.y,a1.z,a1.w};
            float bv[8] = {b0.x,b0.y,b0.z,b0.w,b1v.x,b1v.y,b1v.z,b1v.w};
            #pragma unroll
            for (int i = 0; i < 8; i++)
                #pragma unroll
                for (int j = 0; j < 8; j++)
                    acc[i][j] = fmaf(av[i], bv[j], acc[i][j]);
        }
        if (nxt) {
            int nb = cur ^ 1;
            As[nb][ak+0][ar] = a_r.x; As[nb][ak+1][ar] = a_r.y;
            As[nb][ak+2][ar] = a_r.z; As[nb][ak+3][ar] = a_r.w;
            Bs[nb][0][tid] = b_r0.x; Bs[nb][1][tid] = b_r0.y;
            Bs[nb][2][tid] = b_r0.z; Bs[nb][3][tid] = b_r0.w;
            Bs[nb][4][tid] = b_r1.x; Bs[nb][5][tid] = b_r1.y;
            Bs[nb][6][tid] = b_r1.z; Bs[nb][7][tid] = b_r1.w;
        }
        __syncthreads();
    }

    int jc = j0 + tj * 8;
    float bb[8];
    #pragma unroll
    for (int j = 0; j < 8; j++) bb[j] = b1[jc+j];
    #pragma unroll
    for (int i = 0; i < 8; i++) {
        int row = row0 + tm * 8 + i;
        float4 v0 = make_float4(acc[i][0]+bb[0], acc[i][1]+bb[1],
                                acc[i][2]+bb[2], acc[i][3]+bb[3]);
        float4 v1 = make_float4(acc[i][4]+bb[4], acc[i][5]+bb[5],
                                acc[i][6]+bb[6], acc[i][7]+bb[7]);
        *(float4*)(C + (size_t)row * Hout + jc)     = v0;
        *(float4*)(C + (size_t)row * Hout + jc + 4) = v1;
    }
}

// smem byte offsets (dynamic). Rows are 128B (64 bf16); 16B units swizzled u^(row&7).
#define WS0HI  0
#define WS0LO  4096
#define WH1HI  8192
#define WH1LO  12288
#define WI1HI  16384
#define WI1LO  20480
#define HS0HI  24576
#define HS0LO  40960
#define HS1HI  57344
#define HS1LO  73728
#define B1S    90112
#define CSOFF  92160
#define SMEMB  94208

// ---- fused 2-layer wavefront recurrence (byte-identical to R14) -----------------
__global__ __launch_bounds__(256)
void rnn6(const float* __restrict__ Whh0, const float* __restrict__ Whh1,
          const float* __restrict__ Wih1,
          const float* __restrict__ bih1, const float* __restrict__ bhh1)
{
    extern __shared__ char smc[];
    float* b1s = (float*)(smc + B1S);
    int*   cs  = (int*)(smc + CSOFF);
    __shared__ unsigned gen_sh;
    unsigned sb32 = (unsigned)__cvta_generic_to_shared(smc);

    int tid = threadIdx.x, cta = blockIdx.x;
    int jt = cta & 15, kc = cta >> 4;
    int j0 = jt * 32, k0 = kc * 64;

    for (int i = tid; i < (16384 * 4) / 16; i += 256)
        ((uint4*)(smc + HS0HI))[i] = make_uint4(0, 0, 0, 0);
    {
        int j = tid >> 3, k8 = (tid & 7) * 8;
        int su = (k8 >> 3) ^ (j & 7);
        const float* srcs[3] = {
            Whh0 + (size_t)(j0 + j) * HH + k0 + k8,
            Whh1 + (size_t)(j0 + j) * HH + k0 + k8,
            Wih1 + (size_t)(j0 + j) * HH + k0 + k8 };
        int dsts[3] = {WS0HI, WH1HI, WI1HI};
        #pragma unroll
        for (int m = 0; m < 3; m++) {
            float4 x = *(const float4*)(srcs[m]);
            float4 y = *(const float4*)(srcs[m] + 4);
            unsigned h0w,h1w,h2w,h3w,l0w,l1w,l2w,l3w;
            split2(x.x, x.y, h0w, l0w); split2(x.z, x.w, h1w, l1w);
            split2(y.x, y.y, h2w, l2w); split2(y.z, y.w, h3w, l3w);
            *(uint4*)(smc + dsts[m] + j * 128 + su * 16) = make_uint4(h0w,h1w,h2w,h3w);
            *(uint4*)(smc + dsts[m] + 4096 + j * 128 + su * 16) = make_uint4(l0w,l1w,l2w,l3w);
        }
    }
    for (int i = tid; i < HH; i += 256) b1s[i] = bih1[i] + bhh1[i];
    for (int i = tid; i < TT; i += 256) cs[i] = g_cnt[i];
    if (tid == 0) gen_sh = g_bar_gen;
    __syncthreads();

    int n = tid >> 1, half = tid & 1;
    int w = tid >> 5, lane = tid & 31;
    int arow = w * 16 + (lane & 7) + ((lane >> 3) & 1) * 8;
    int asel = (lane >> 4) & 1;
    int abase = arow * 128;
    int bgrp = ((lane >> 4) & 1) * 8 + (lane & 7);
    int bsel = (lane >> 3) & 1;
    int orow = w * 16 + (lane >> 2);
    int ocol = j0 + (lane & 3) * 2;

    for (int s = 0; s <= TT; s++) {
        int cnt0 = (s < TT) ? cs[s] : 0;
        int cnt1 = (s > 0) ? cs[s - 1] : 0;
        int sb = max(cnt0, cnt1);
        if (sb == 0) break;

        if (n < sb) {
            size_t eoff = (size_t)n * HH + k0 + half * 32;
            const uint4* shi = (const uint4*)(g_hb0hi + eoff);
            const uint4* slo = (const uint4*)(g_hb0lo + eoff);
            int swbase = n * 128;
            #pragma unroll
            for (int q = 0; q < 4; q++) {
                int su = (half * 4 + q) ^ (n & 7);
                *(uint4*)(smc + HS0HI + swbase + su * 16) = __ldcg(shi + q);
                *(uint4*)(smc + HS0LO + swbase + su * 16) = __ldcg(slo + q);
            }
        }
        if (n < cnt1) {
            size_t eoff = (size_t)n * HH + k0 + half * 32;
            const uint4* shi = (const uint4*)(g_hb1hi + eoff);
            const uint4* slo = (const uint4*)(g_hb1lo + eoff);
            int swbase = n * 128;
            #pragma unroll
            for (int q = 0; q < 4; q++) {
                int su = (half * 4 + q) ^ (n & 7);
                *(uint4*)(smc + HS1HI + swbase + su * 16) = __ldcg(shi + q);
                *(uint4*)(smc + HS1LO + swbase + su * 16) = __ldcg(slo + q);
            }
        }
        __syncthreads();

        bool act0 = (w * 16 < cnt0), act1 = (w * 16 < cnt1);
        if (act0 | act1) {
            float acc0[4][4] = {}, acc1[4][4] = {};
            #pragma unroll
            for (int kt = 0; kt < 4; kt++) {
                int au = ((kt * 2 + asel) ^ (arow & 7)) * 16;
                unsigned a0h[4], a0l[4], a1h[4], a1l[4];
                ldsm_x4(a0h, sb32 + HS0HI + abase + au);
                ldsm_x4(a0l, sb32 + HS0LO + abase + au);
                if (act1) {
                    ldsm_x4(a1h, sb32 + HS1HI + abase + au);
                    ldsm_x4(a1l, sb32 + HS1LO + abase + au);
                }
                #pragma unroll
                for (int ntp = 0; ntp < 2; ntp++) {
                    int brr = ntp * 16 + bgrp;
                    int boff = brr * 128 + (((kt * 2 + bsel) ^ (brr & 7)) * 16);
                    unsigned b4[4];
                    if (act0) {
                        ldsm_x4(b4, sb32 + WS0HI + boff);
                        mma_bf16(acc0[ntp*2],   a0h, b4);
                        mma_bf16(acc0[ntp*2+1], a0h, b4 + 2);
                        mma_bf16(acc0[ntp*2],   a0l, b4);
                        mma_bf16(acc0[ntp*2+1], a0l, b4 + 2);
                        ldsm_x4(b4, sb32 + WS0LO + boff);
                        mma_bf16(acc0[ntp*2],   a0h, b4);
                        mma_bf16(acc0[ntp*2+1], a0h, b4 + 2);
                    }
                    if (act1) {
                        ldsm_x4(b4, sb32 + WH1HI + boff);
                        mma_bf16(acc1[ntp*2],   a1h, b4);
                        mma_bf16(acc1[ntp*2+1], a1h, b4 + 2);
                        mma_bf16(acc1[ntp*2],   a1l, b4);
                        mma_bf16(acc1[ntp*2+1], a1l, b4 + 2);
                        ldsm_x4(b4, sb32 + WH1LO + boff);
                        mma_bf16(acc1[ntp*2],   a1h, b4);
                        mma_bf16(acc1[ntp*2+1], a1h, b4 + 2);
                        ldsm_x4(b4, sb32 + WI1HI + boff);
                        mma_bf16(acc1[ntp*2],   a0h, b4);
                        mma_bf16(acc1[ntp*2+1], a0h, b4 + 2);
                        mma_bf16(acc1[ntp*2],   a0l, b4);
                        mma_bf16(acc1[ntp*2+1], a0l, b4 + 2);
                        ldsm_x4(b4, sb32 + WI1LO + boff);
                        mma_bf16(acc1[ntp*2],   a0h, b4);
                        mma_bf16(acc1[ntp*2+1], a0h, b4 + 2);
                    }
                }
            }
            size_t pbase = (size_t)kc * NH;
            #pragma unroll
            for (int nt = 0; nt < 4; nt++) {
                int c = ocol + nt * 8;
                if (act0) {
                    *(float2*)&g_part0[pbase + (size_t)orow * HH + c] =
                        make_float2(acc0[nt][0], acc0[nt][1]);
                    *(float2*)&g_part0[pbase + (size_t)(orow + 8) * HH + c] =
                        make_float2(acc0[nt][2], acc0[nt][3]);
                }
                if (act1) {
                    *(float2*)&g_part1[pbase + (size_t)orow * HH + c] =
                        make_float2(acc1[nt][0], acc1[nt][1]);
                    *(float2*)&g_part1[pbase + (size_t)(orow + 8) * HH + c] =
                        make_float2(acc1[nt][2], acc1[nt][3]);
                }
            }
        }

        grid_barrier(&gen_sh, RNN_BLOCKS);

        if (cnt0 > 0) {
            const float4* xp4 = (const float4*)(g_xp + (size_t)s * NH);
            int total4 = cnt0 * (HH / 4);
            for (int v = cta * 256 + tid; v < total4; v += RNN_BLOCKS * 256) {
                float4 sum = xp4[v];
                #pragma unroll
                for (int p = 0; p < 8; p++) {
                    float4 pp = __ldcg((const float4*)g_part0 + (size_t)p * (NH/4) + v);
                    sum.x += pp.x; sum.y += pp.y; sum.z += pp.z; sum.w += pp.w;
                }
                float t0 = tanhf(sum.x), t1 = tanhf(sum.y);
                float t2 = tanhf(sum.z), t3 = tanhf(sum.w);
                unsigned h01, l01, h23, l23;
                split2(t0, t1, h01, l01); split2(t2, t3, h23, l23);
                ((uint2*)g_hb0hi)[v] = make_uint2(h01, h23);
                ((uint2*)g_hb0lo)[v] = make_uint2(l01, l23);
            }
        }
        if (cnt1 > 0) {
            int total4 = cnt1 * (HH / 4);
            for (int v = cta * 256 + tid; v < total4; v += RNN_BLOCKS * 256) {
                float4 sum = *(const float4*)&b1s[(v * 4) & (HH - 1)];
                #pragma unroll
                for (int p = 0; p < 8; p++) {
                    float4 pp = __ldcg((const float4*)g_part1 + (size_t)p * (NH/4) + v);
                    sum.x += pp.x; sum.y += pp.y; sum.z += pp.z; sum.w += pp.w;
                }
                float t0 = tanhf(sum.x), t1 = tanhf(sum.y);
                float t2 = tanhf(sum.z), t3 = tanhf(sum.w);
                unsigned h01, l01, h23, l23;
                split2(t0, t1, h01, l01); split2(t2, t3, h23, l23);
                ((uint2*)g_hb1hi)[v] = make_uint2(h01, h23);
                ((uint2*)g_hb1lo)[v] = make_uint2(l01, l23);
            }
        }

        grid_barrier(&gen_sh, RNN_BLOCKS);
    }
}

extern "C" void kernel_launch(void* const* d_in, const int* in_sizes, int n_in,
                              void* d_out, int out_size) {
    const float* x    = (const float*)d_in[0];
    const float* h0   = (const float*)d_in[1];
    const int*   len  = (const int*)  d_in[2];
    const float* Wih0 = (const float*)d_in[3];
    const float* bih0 = (const float*)d_in[4];
    const float* Whh0 = (const float*)d_in[5];
    const float* bhh0 = (const float*)d_in[6];
    const float* Wih1 = (const float*)d_in[7];
    const float* bih1 = (const float*)d_in[8];
    const float* Whh1 = (const float*)d_in[9];
    const float* bhh1 = (const float*)d_in[10];
    const float* Wfc  = (const float*)d_in[11];
    const float* bfc  = (const float*)d_in[12];
    float* out = (float*)d_out;

    static int smem_set = 0;
    if (!smem_set) {
        cudaFuncSetAttribute(rnn6, cudaFuncAttributeMaxDynamicSharedMemorySize, SMEMB);
        cudaFuncSetAttribute(xp_hmma, cudaFuncAttributeMaxDynamicSharedMemorySize, XSMEM);
        smem_set = 1;
    }

    count_kernel<<<1, TT>>>(len);
    init_h_kernel<<<NH/256, 256>>>(h0);

    // layer-0 xproj (+ both layer-0 biases) on tensor cores
    xp_hmma<<<dim3(4, TT), 256, XSMEM>>>(x, Wih0, bih0, bhh0);

    // fused 2-layer wavefront recurrence (tensor-core phase 1)
    rnn6<<<RNN_BLOCKS, 256, SMEMB>>>(Whh0, Whh1, Wih1, bih1, bhh1);

    copy_h_kernel<<<NH/256, 256>>>(out);

    // logits = h1_final @ Wfc^T + bfc
    gemm64<<<dim3(CC/128, NN/64), 128>>>(Wfc, bfc, out, HH, CC);
}

// round 17
// speedup vs baseline: 3.4414x; 1.1472x over previous
#include <cuda_runtime.h>
#include <cuda_bf16.h>
#include <math.h>

#define TT 512
#define NN 128
#define II 256
#define HH 512
#define CC 128
#define NH (NN*HH)
#define RNN_BLOCKS 128
#define H_OFF (NN*CC)

__device__ float g_xp[TT*NN*HH];
__device__ __align__(16) __nv_bfloat16 g_hb0hi[NH];
__device__ __align__(16) __nv_bfloat16 g_hb0lo[NH];
__device__ __align__(16) __nv_bfloat16 g_hb1hi[NH];
__device__ __align__(16) __nv_bfloat16 g_hb1lo[NH];
__device__ float g_hf[NH];
__device__ float g_part0[8*NH];
__device__ float g_part1[8*NH];
__device__ int   g_cnt[TT];
__device__ unsigned g_bar_count;
__device__ volatile unsigned g_bar_gen;

// ---- grid barrier: PROVEN flat idiom. DO NOT CHANGE. ---------------------------
__device__ __forceinline__ void grid_barrier(unsigned* gen_sh, int nblk) {
    __syncthreads();
    if (threadIdx.x == 0) {
        unsigned g = *gen_sh;
        __threadfence();
        unsigned prev = atomicAdd(&g_bar_count, 1u);
        if (prev == (unsigned)(nblk - 1)) {
            g_bar_count = 0u;
            __threadfence();
            g_bar_gen = g + 1u;
        } else {
            while (g_bar_gen == g) { }
        }
        *gen_sh = g + 1u;
    }
    __syncthreads();
}

__global__ void count_kernel(const int* __restrict__ len) {
    int t = threadIdx.x, c = 0;
    #pragma unroll 8
    for (int n = 0; n < NN; n++) c += (len[n] > t) ? 1 : 0;
    g_cnt[t] = c;
}

__global__ void init_h_kernel(const float* __restrict__ h0) {
    int i = blockIdx.x * blockDim.x + threadIdx.x;
    if (i < NH) {
        float a = h0[i];
        __nv_bfloat16 ah = __float2bfloat16(a);
        g_hb0hi[i] = ah;
        g_hb0lo[i] = __float2bfloat16(a - __bfloat162float(ah));
        float b = h0[NH + i];
        __nv_bfloat16 bh = __float2bfloat16(b);
        g_hb1hi[i] = bh;
        g_hb1lo[i] = __float2bfloat16(b - __bfloat162float(bh));
    }
}

__global__ void copy_h_kernel(float* __restrict__ dout) {
    int i = blockIdx.x * blockDim.x + threadIdx.x;
    if (i < NH) {
        float v0 = __bfloat162float(g_hb0hi[i]) + __bfloat162float(g_hb0lo[i]);
        float v1 = __bfloat162float(g_hb1hi[i]) + __bfloat162float(g_hb1lo[i]);
        dout[H_OFF + i]      = v0;
        dout[H_OFF + NH + i] = v1;
        g_hf[i] = v1;
    }
}

// ---- helpers ---------------------------------------------------------------------
__device__ __forceinline__ void mma_bf16(float* d, const unsigned* a, const unsigned* b) {
    asm volatile(
        "mma.sync.aligned.m16n8k16.row.col.f32.bf16.bf16.f32 "
        "{%0,%1,%2,%3}, {%4,%5,%6,%7}, {%8,%9}, {%0,%1,%2,%3};"
        : "+f"(d[0]), "+f"(d[1]), "+f"(d[2]), "+f"(d[3])
        : "r"(a[0]), "r"(a[1]), "r"(a[2]), "r"(a[3]), "r"(b[0]), "r"(b[1]));
}
__device__ __forceinline__ void ldsm_x4(unsigned* r, unsigned addr) {
    asm volatile("ldmatrix.sync.aligned.m8n8.x4.shared.b16 {%0,%1,%2,%3}, [%4];"
        : "=r"(r[0]), "=r"(r[1]), "=r"(r[2]), "=r"(r[3]) : "r"(addr));
}
__device__ __forceinline__ void split2(float a, float b, unsigned& hi, unsigned& lo) {
    __nv_bfloat162 h2 = __floats2bfloat162_rn(a, b);
    float ra = a - __bfloat162float(__low2bfloat16(h2));
    float rb = b - __bfloat162float(__high2bfloat16(h2));
    __nv_bfloat162 l2 = __floats2bfloat162_rn(ra, rb);
    hi = *(unsigned*)&h2; lo = *(unsigned*)&l2;
}

// ---- xp0 GEMM on tensor cores (unchanged, proven) --------------------------------
#define XHI 0
#define XLO 16384
#define WHI 32768
#define WLO 49152
#define XBS 65536
#define XSMEM 66048
__global__ __launch_bounds__(256)
void xp_hmma(const float* __restrict__ x, const float* __restrict__ Wih0,
             const float* __restrict__ bih0, const float* __restrict__ bhh0)
{
    int t = blockIdx.y;
    int cnt = g_cnt[t];
    if (cnt == 0) return;
    int jt = blockIdx.x;
    extern __shared__ char smc[];
    float* bsum = (float*)(smc + XBS);
    unsigned sb32 = (unsigned)__cvta_generic_to_shared(smc);

    int tid = threadIdx.x;
    int w = tid >> 5, lane = tid & 31;
    int arow = w * 16 + (lane & 7) + ((lane >> 3) & 1) * 8;
    int asel = (lane >> 4) & 1;
    int abase = arow * 128;
    int bgrp = ((lane >> 4) & 1) * 8 + (lane & 7);
    int bsel = (lane >> 3) & 1;

    if (tid < 128) bsum[tid] = bih0[jt * 128 + tid] + bhh0[jt * 128 + tid];

    bool actw = (w * 16 < cnt);
    float acc[16][4] = {};

    int r = tid >> 1, half = tid & 1;
    #pragma unroll 1
    for (int kc = 0; kc < 4; kc++) {
        __syncthreads();
        {
            const float4* xs = (const float4*)(x + ((size_t)t * NN + r) * II + kc * 64 + half * 32);
            const float4* ws = (const float4*)(Wih0 + (size_t)(jt * 128 + r) * II + kc * 64 + half * 32);
            int swbase = r * 128;
            #pragma unroll
            for (int q = 0; q < 4; q++) {
                int su = (half * 4 + q) ^ (r & 7);
                float4 a = xs[q * 2], b = xs[q * 2 + 1];
                unsigned h0w,h1w,h2w,h3w,l0w,l1w,l2w,l3w;
                split2(a.x, a.y, h0w, l0w); split2(a.z, a.w, h1w, l1w);
                split2(b.x, b.y, h2w, l2w); split2(b.z, b.w, h3w, l3w);
                *(uint4*)(smc + XHI + swbase + su * 16) = make_uint4(h0w,h1w,h2w,h3w);
                *(uint4*)(smc + XLO + swbase + su * 16) = make_uint4(l0w,l1w,l2w,l3w);
                a = ws[q * 2]; b = ws[q * 2 + 1];
                split2(a.x, a.y, h0w, l0w); split2(a.z, a.w, h1w, l1w);
                split2(b.x, b.y, h2w, l2w); split2(b.z, b.w, h3w, l3w);
                *(uint4*)(smc + WHI + swbase + su * 16) = make_uint4(h0w,h1w,h2w,h3w);
                *(uint4*)(smc + WLO + swbase + su * 16) = make_uint4(l0w,l1w,l2w,l3w);
            }
        }
        __syncthreads();

        if (actw) {
            #pragma unroll
            for (int kt = 0; kt < 4; kt++) {
                int au = ((kt * 2 + asel) ^ (arow & 7)) * 16;
                unsigned ah[4], al[4];
                ldsm_x4(ah, sb32 + XHI + abase + au);
                ldsm_x4(al, sb32 + XLO + abase + au);
                #pragma unroll
                for (int ntp = 0; ntp < 8; ntp++) {
                    int brr = ntp * 16 + bgrp;
                    int boff = brr * 128 + (((kt * 2 + bsel) ^ (brr & 7)) * 16);
                    unsigned b4[4];
                    ldsm_x4(b4, sb32 + WHI + boff);
                    mma_bf16(acc[ntp*2],   ah, b4);
                    mma_bf16(acc[ntp*2+1], ah, b4 + 2);
                    mma_bf16(acc[ntp*2],   al, b4);
                    mma_bf16(acc[ntp*2+1], al, b4 + 2);
                    ldsm_x4(b4, sb32 + WLO + boff);
                    mma_bf16(acc[ntp*2],   ah, b4);
                    mma_bf16(acc[ntp*2+1], ah, b4 + 2);
                }
            }
        }
    }

    if (actw) {
        int lr = lane >> 2, lc = (lane & 3) * 2;
        int r0 = w * 16 + lr;
        #pragma unroll
        for (int nt = 0; nt < 16; nt++) {
            int cl = nt * 8 + lc;
            float b0 = bsum[cl], b1 = bsum[cl + 1];
            if (r0 < cnt)
                *(float2*)&g_xp[((size_t)t * NN + r0) * HH + jt * 128 + cl] =
                    make_float2(acc[nt][0] + b0, acc[nt][1] + b1);
            if (r0 + 8 < cnt)
                *(float2*)&g_xp[((size_t)t * NN + r0 + 8) * HH + jt * 128 + cl] =
                    make_float2(acc[nt][2] + b0, acc[nt][3] + b1);
        }
    }
}

// ---- logits GEMM (fp32, unchanged) ------------------------------------------------
__global__ __launch_bounds__(128)
void gemm64(const float* __restrict__ W, const float* __restrict__ b1,
            float* __restrict__ C, int K, int Hout)
{
    int row0 = blockIdx.y * 64;
    int j0 = blockIdx.x * 128;
    int tid = threadIdx.x;

    __shared__ float As[2][8][68];
    __shared__ float Bs[2][8][132];

    int ar = tid >> 1;
    int ak = (tid & 1) * 4;
    const float* Ap = g_hf + (size_t)(row0 + ar) * K + ak;
    const float* Wp = W + (size_t)(j0 + tid) * K;
    int KT = K >> 3;

    float4 a_r  = *(const float4*)(Ap);
    float4 b_r0 = *(const float4*)(Wp);
    float4 b_r1 = *(const float4*)(Wp + 4);
    As[0][ak+0][ar] = a_r.x; As[0][ak+1][ar] = a_r.y;
    As[0][ak+2][ar] = a_r.z; As[0][ak+3][ar] = a_r.w;
    Bs[0][0][tid] = b_r0.x; Bs[0][1][tid] = b_r0.y;
    Bs[0][2][tid] = b_r0.z; Bs[0][3][tid] = b_r0.w;
    Bs[0][4][tid] = b_r1.x; Bs[0][5][tid] = b_r1.y;
    Bs[0][6][tid] = b_r1.z; Bs[0][7][tid] = b_r1.w;
    __syncthreads();

    int tm = tid & 7;
    int tj = tid >> 3;
    float acc[8][8] = {};

    for (int kt = 0; kt < KT; kt++) {
        int cur = kt & 1;
        bool nxt = (kt + 1 < KT);
        if (nxt) {
            int k0 = (kt + 1) << 3;
            a_r  = *(const float4*)(Ap + k0);
            b_r0 = *(const float4*)(Wp + k0);
            b_r1 = *(const float4*)(Wp + k0 + 4);
        }
        #pragma unroll
        for (int kk = 0; kk < 8; kk++) {
            float4 a0 = *(const float4*)&As[cur][kk][tm*8];
            float4 a1 = *(const float4*)&As[cur][kk][tm*8+4];
            float4 b0 = *(const float4*)&Bs[cur][kk][tj*8];
            float4 b1v= *(const float4*)&Bs[cur][kk][tj*8+4];
            float av[8] = {a0.x,a0.y,a0.z,a0.w,a1.x,a1.y,a1.z,a1.w};
            float bv[8] = {b0.x,b0.y,b0.z,b0.w,b1v.x,b1v.y,b1v.z,b1v.w};
            #pragma unroll
            for (int i = 0; i < 8; i++)
                #pragma unroll
                for (int j = 0; j < 8; j++)
                    acc[i][j] = fmaf(av[i], bv[j], acc[i][j]);
        }
        if (nxt) {
            int nb = cur ^ 1;
            As[nb][ak+0][ar] = a_r.x; As[nb][ak+1][ar] = a_r.y;
            As[nb][ak+2][ar] = a_r.z; As[nb][ak+3][ar] = a_r.w;
            Bs[nb][0][tid] = b_r0.x; Bs[nb][1][tid] = b_r0.y;
            Bs[nb][2][tid] = b_r0.z; Bs[nb][3][tid] = b_r0.w;
            Bs[nb][4][tid] = b_r1.x; Bs[nb][5][tid] = b_r1.y;
            Bs[nb][6][tid] = b_r1.z; Bs[nb][7][tid] = b_r1.w;
        }
        __syncthreads();
    }

    int jc = j0 + tj * 8;
    float bb[8];
    #pragma unroll
    for (int j = 0; j < 8; j++) bb[j] = b1[jc+j];
    #pragma unroll
    for (int i = 0; i < 8; i++) {
        int row = row0 + tm * 8 + i;
        float4 v0 = make_float4(acc[i][0]+bb[0], acc[i][1]+bb[1],
                                acc[i][2]+bb[2], acc[i][3]+bb[3]);
        float4 v1 = make_float4(acc[i][4]+bb[4], acc[i][5]+bb[5],
                                acc[i][6]+bb[6], acc[i][7]+bb[7]);
        *(float4*)(C + (size_t)row * Hout + jc)     = v0;
        *(float4*)(C + (size_t)row * Hout + jc + 4) = v1;
    }
}

// smem byte offsets; 128B rows, 16B units swizzled u^(row&7)
#define WS0HI  0
#define WS0LO  4096
#define WH1HI  8192
#define WH1LO  12288
#define WI1HI  16384
#define WI1LO  20480
#define HS0HI  24576
#define HS0LO  40960
#define HS1HI  57344
#define HS1LO  73728
#define B1S    90112
#define CSOFF  92160
#define SMEMB  94208

// ---- fused 2-layer wavefront recurrence (R14/R15 dataflow + 3 micro-opts) --------
__global__ __launch_bounds__(256)
void rnn6(const float* __restrict__ Whh0, const float* __restrict__ Whh1,
          const float* __restrict__ Wih1,
          const float* __restrict__ bih1, const float* __restrict__ bhh1)
{
    extern __shared__ char smc[];
    float* b1s = (float*)(smc + B1S);
    int*   cs  = (int*)(smc + CSOFF);
    __shared__ unsigned gen_sh;
    unsigned sb32 = (unsigned)__cvta_generic_to_shared(smc);

    int tid = threadIdx.x, cta = blockIdx.x;
    int jt = cta & 15, kc = cta >> 4;
    int j0 = jt * 32, k0 = kc * 64;

    for (int i = tid; i < (16384 * 4) / 16; i += 256)
        ((uint4*)(smc + HS0HI))[i] = make_uint4(0, 0, 0, 0);
    {
        int j = tid >> 3, k8 = (tid & 7) * 8;
        int su = (k8 >> 3) ^ (j & 7);
        const float* srcs[3] = {
            Whh0 + (size_t)(j0 + j) * HH + k0 + k8,
            Whh1 + (size_t)(j0 + j) * HH + k0 + k8,
            Wih1 + (size_t)(j0 + j) * HH + k0 + k8 };
        int dsts[3] = {WS0HI, WH1HI, WI1HI};
        #pragma unroll
        for (int m = 0; m < 3; m++) {
            float4 x = *(const float4*)(srcs[m]);
            float4 y = *(const float4*)(srcs[m] + 4);
            unsigned h0w,h1w,h2w,h3w,l0w,l1w,l2w,l3w;
            split2(x.x, x.y, h0w, l0w); split2(x.z, x.w, h1w, l1w);
            split2(y.x, y.y, h2w, l2w); split2(y.z, y.w, h3w, l3w);
            *(uint4*)(smc + dsts[m] + j * 128 + su * 16) = make_uint4(h0w,h1w,h2w,h3w);
            *(uint4*)(smc + dsts[m] + 4096 + j * 128 + su * 16) = make_uint4(l0w,l1w,l2w,l3w);
        }
    }
    for (int i = tid; i < HH; i += 256) b1s[i] = bih1[i] + bhh1[i];
    for (int i = tid; i < TT; i += 256) cs[i] = g_cnt[i];
    if (tid == 0) gen_sh = g_bar_gen;
    __syncthreads();

    int n = tid >> 1, half = tid & 1;
    int w = tid >> 5, lane = tid & 31;
    int arow = w * 16 + (lane & 7) + ((lane >> 3) & 1) * 8;
    int asel = (lane >> 4) & 1;
    int abase = arow * 128;
    int bgrp = ((lane >> 4) & 1) * 8 + (lane & 7);
    int bsel = (lane >> 3) & 1;
    int orow = w * 16 + (lane >> 2);
    int ocol = j0 + (lane & 3) * 2;

    // ---- hoist static W fragments (WS0 hi/lo, WI1 hi/lo): 128 regs, loaded once --
    unsigned wS0h[8][4], wS0l[8][4], wI1h[8][4], wI1l[8][4];
    #pragma unroll
    for (int kt = 0; kt < 4; kt++)
        #pragma unroll
        for (int ntp = 0; ntp < 2; ntp++) {
            int brr = ntp * 16 + bgrp;
            int boff = brr * 128 + (((kt * 2 + bsel) ^ (brr & 7)) * 16);
            int idx = kt * 2 + ntp;
            ldsm_x4(wS0h[idx], sb32 + WS0HI + boff);
            ldsm_x4(wS0l[idx], sb32 + WS0LO + boff);
            ldsm_x4(wI1h[idx], sb32 + WI1HI + boff);
            ldsm_x4(wI1l[idx], sb32 + WI1LO + boff);
        }

    // phase-2 element ownership: CTAs 0-63 -> layer0, CTAs 64-127 -> layer1
    bool isL0 = (cta < 64);
    int pv = (cta & 63) * 256 + tid;   // element (float4 granularity) within layer

    for (int s = 0; s <= TT; s++) {
        int cnt0 = (s < TT) ? cs[s] : 0;
        int cnt1 = (s > 0) ? cs[s - 1] : 0;
        int sb = max(cnt0, cnt1);
        if (sb == 0) break;

        // ---- stage pre-split h -> smem (16B copies, swizzled) ----
        if (n < sb) {
            size_t eoff = (size_t)n * HH + k0 + half * 32;
            const uint4* shi = (const uint4*)(g_hb0hi + eoff);
            const uint4* slo = (const uint4*)(g_hb0lo + eoff);
            int swbase = n * 128;
            #pragma unroll
            for (int q = 0; q < 4; q++) {
                int su = (half * 4 + q) ^ (n & 7);
                *(uint4*)(smc + HS0HI + swbase + su * 16) = __ldcg(shi + q);
                *(uint4*)(smc + HS0LO + swbase + su * 16) = __ldcg(slo + q);
            }
        }
        if (n < cnt1) {
            size_t eoff = (size_t)n * HH + k0 + half * 32;
            const uint4* shi = (const uint4*)(g_hb1hi + eoff);
            const uint4* slo = (const uint4*)(g_hb1lo + eoff);
            int swbase = n * 128;
            #pragma unroll
            for (int q = 0; q < 4; q++) {
                int su = (half * 4 + q) ^ (n & 7);
                *(uint4*)(smc + HS1HI + swbase + su * 16) = __ldcg(shi + q);
                *(uint4*)(smc + HS1LO + swbase + su * 16) = __ldcg(slo + q);
            }
        }
        __syncthreads();

        // ---- phase 1: HMMA GEMMs (hoisted WS0/WI1 fragments) ----
        bool act0 = (w * 16 < cnt0), act1 = (w * 16 < cnt1);
        if (act0 | act1) {
            float acc0[4][4] = {}, acc1[4][4] = {};
            #pragma unroll
            for (int kt = 0; kt < 4; kt++) {
                int au = ((kt * 2 + asel) ^ (arow & 7)) * 16;
                unsigned a0h[4], a0l[4], a1h[4], a1l[4];
                ldsm_x4(a0h, sb32 + HS0HI + abase + au);
                ldsm_x4(a0l, sb32 + HS0LO + abase + au);
                if (act1) {
                    ldsm_x4(a1h, sb32 + HS1HI + abase + au);
                    ldsm_x4(a1l, sb32 + HS1LO + abase + au);
                }
                #pragma unroll
                for (int ntp = 0; ntp < 2; ntp++) {
                    int idx = kt * 2 + ntp;
                    if (act0) {
                        mma_bf16(acc0[ntp*2],   a0h, wS0h[idx]);
                        mma_bf16(acc0[ntp*2+1], a0h, wS0h[idx] + 2);
                        mma_bf16(acc0[ntp*2],   a0l, wS0h[idx]);
                        mma_bf16(acc0[ntp*2+1], a0l, wS0h[idx] + 2);
                        mma_bf16(acc0[ntp*2],   a0h, wS0l[idx]);
                        mma_bf16(acc0[ntp*2+1], a0h, wS0l[idx] + 2);
                    }
                    if (act1) {
                        int brr = ntp * 16 + bgrp;
                        int boff = brr * 128 + (((kt * 2 + bsel) ^ (brr & 7)) * 16);
                        unsigned b4[4];
                        ldsm_x4(b4, sb32 + WH1HI + boff);
                        mma_bf16(acc1[ntp*2],   a1h, b4);
                        mma_bf16(acc1[ntp*2+1], a1h, b4 + 2);
                        mma_bf16(acc1[ntp*2],   a1l, b4);
                        mma_bf16(acc1[ntp*2+1], a1l, b4 + 2);
                        ldsm_x4(b4, sb32 + WH1LO + boff);
                        mma_bf16(acc1[ntp*2],   a1h, b4);
                        mma_bf16(acc1[ntp*2+1], a1h, b4 + 2);
                        mma_bf16(acc1[ntp*2],   a0h, wI1h[idx]);
                        mma_bf16(acc1[ntp*2+1], a0h, wI1h[idx] + 2);
                        mma_bf16(acc1[ntp*2],   a0l, wI1h[idx]);
                        mma_bf16(acc1[ntp*2+1], a0l, wI1h[idx] + 2);
                        mma_bf16(acc1[ntp*2],   a0h, wI1l[idx]);
                        mma_bf16(acc1[ntp*2+1], a0h, wI1l[idx] + 2);
                    }
                }
            }
            size_t pbase = (size_t)kc * NH;
            #pragma unroll
            for (int nt = 0; nt < 4; nt++) {
                int c = ocol + nt * 8;
                if (act0) {
                    *(float2*)&g_part0[pbase + (size_t)orow * HH + c] =
                        make_float2(acc0[nt][0], acc0[nt][1]);
                    *(float2*)&g_part0[pbase + (size_t)(orow + 8) * HH + c] =
                        make_float2(acc0[nt][2], acc0[nt][3]);
                }
                if (act1) {
                    *(float2*)&g_part1[pbase + (size_t)orow * HH + c] =
                        make_float2(acc1[nt][0], acc1[nt][1]);
                    *(float2*)&g_part1[pbase + (size_t)(orow + 8) * HH + c] =
                        make_float2(acc1[nt][2], acc1[nt][3]);
                }
            }
        }

        // xp prefetch (g_xp static after xp_hmma -> legal pre-barrier)
        bool has = isL0 ? (pv < cnt0 * (HH / 4)) : (pv < cnt1 * (HH / 4));
        float4 xpre = make_float4(0.f, 0.f, 0.f, 0.f);
        if (isL0 && has)
            xpre = __ldcg((const float4*)(g_xp + (size_t)s * NH) + pv);

        grid_barrier(&gen_sh, RNN_BLOCKS);

        // ---- phase 2: one layer per CTA half, one element per thread ----
        if (has) {
            float4 sum = isL0 ? xpre : *(const float4*)&b1s[(pv * 4) & (HH - 1)];
            const float4* pb = (const float4*)(isL0 ? g_part0 : g_part1);
            #pragma unroll
            for (int p = 0; p < 8; p++) {
                float4 pp = __ldcg(pb + (size_t)p * (NH/4) + pv);
                sum.x += pp.x; sum.y += pp.y; sum.z += pp.z; sum.w += pp.w;
            }
            float t0 = tanhf(sum.x), t1 = tanhf(sum.y);
            float t2 = tanhf(sum.z), t3 = tanhf(sum.w);
            unsigned h01, l01, h23, l23;
            split2(t0, t1, h01, l01); split2(t2, t3, h23, l23);
            if (isL0) {
                ((uint2*)g_hb0hi)[pv] = make_uint2(h01, h23);
                ((uint2*)g_hb0lo)[pv] = make_uint2(l01, l23);
            } else {
                ((uint2*)g_hb1hi)[pv] = make_uint2(h01, h23);
                ((uint2*)g_hb1lo)[pv] = make_uint2(l01, l23);
            }
        }

        grid_barrier(&gen_sh, RNN_BLOCKS);
    }
}

extern "C" void kernel_launch(void* const* d_in, const int* in_sizes, int n_in,
                              void* d_out, int out_size) {
    const float* x    = (const float*)d_in[0];
    const float* h0   = (const float*)d_in[1];
    const int*   len  = (const int*)  d_in[2];
    const float* Wih0 = (const float*)d_in[3];
    const float* bih0 = (const float*)d_in[4];
    const float* Whh0 = (const float*)d_in[5];
    const float* bhh0 = (const float*)d_in[6];
    const float* Wih1 = (const float*)d_in[7];
    const float* bih1 = (const float*)d_in[8];
    const float* Whh1 = (const float*)d_in[9];
    const float* bhh1 = (const float*)d_in[10];
    const float* Wfc  = (const float*)d_in[11];
    const float* bfc  = (const float*)d_in[12];
    float* out = (float*)d_out;

    static int smem_set = 0;
    if (!smem_set) {
        cudaFuncSetAttribute(rnn6, cudaFuncAttributeMaxDynamicSharedMemorySize, SMEMB);
        cudaFuncSetAttribute(xp_hmma, cudaFuncAttributeMaxDynamicSharedMemorySize, XSMEM);
        smem_set = 1;
    }

    count_kernel<<<1, TT>>>(len);
    init_h_kernel<<<NH/256, 256>>>(h0);

    xp_hmma<<<dim3(4, TT), 256, XSMEM>>>(x, Wih0, bih0, bhh0);
    rnn6<<<RNN_BLOCKS, 256, SMEMB>>>(Whh0, Whh1, Wih1, bih1, bhh1);
    copy_h_kernel<<<NH/256, 256>>>(out);
    gemm64<<<dim3(CC/128, NN/64), 128>>>(Wfc, bfc, out, HH, CC);
}